// round 4
// baseline (speedup 1.0000x reference)
#include <cuda_runtime.h>
#include <cstdint>

#define TD 2048      // D = 2*W
#define NB 2048      // BATCH
#define NP 8         // P previous windows
#define KOM 50       // OMEGA
#define CAP 64       // sparse capacity per row (>= OMEGA + tie slack)

// -------- scratch (device globals; no runtime allocation allowed) --------
__device__ float g_B[(size_t)NB * TD];     // B = x @ W_d^T
__device__ float g_M[(size_t)TD * TD];     // M = W_d @ W_d
__device__ float g_T[(size_t)NB * TD];     // dense temp
__device__ float g_V[(size_t)NB * TD];     // v, then z_att
__device__ float g_vals[NB * CAP];
__device__ int   g_cols[NB * CAP];
__device__ int   g_cnt[NB];
__device__ float g_attraw[NP * NB];
__device__ float g_att[NP * NB];
__device__ float g_mD[1024];

// ---------------- fp32 tiled GEMM: C = A*op(B) (+ Base) ----------------
// C[m,n] = (ADD_BASE? Base[m,n]:0) + sum_k A[m,k] * (TRANS_B ? Bm[n,k] : Bm[k,n])
template<int TRANS_B, int ADD_BASE>
__global__ __launch_bounds__(256) void sgemm_kernel(
    const float* __restrict__ A, const float* __restrict__ Bm,
    const float* __restrict__ Base, float* __restrict__ C)
{
    __shared__ float As[8][128];
    __shared__ float Bs[8][132];
    const int tid = threadIdx.x;
    const int m0 = blockIdx.y * 128, n0 = blockIdx.x * 128;
    const int tx = tid & 15, ty = tid >> 4;
    const int rowA = tid >> 1, kA = (tid & 1) * 4;
    const int kB = tid >> 5, nB = (tid & 31) * 4;
    float acc[8][8];
#pragma unroll
    for (int i = 0; i < 8; i++)
#pragma unroll
        for (int j = 0; j < 8; j++) acc[i][j] = 0.f;

    for (int k0 = 0; k0 < TD; k0 += 8) {
        float4 av = *(const float4*)(A + (size_t)(m0 + rowA) * TD + k0 + kA);
        As[kA + 0][rowA] = av.x; As[kA + 1][rowA] = av.y;
        As[kA + 2][rowA] = av.z; As[kA + 3][rowA] = av.w;
        if (TRANS_B) {
            float4 bv = *(const float4*)(Bm + (size_t)(n0 + rowA) * TD + k0 + kA);
            Bs[kA + 0][rowA] = bv.x; Bs[kA + 1][rowA] = bv.y;
            Bs[kA + 2][rowA] = bv.z; Bs[kA + 3][rowA] = bv.w;
        } else {
            float4 bv = *(const float4*)(Bm + (size_t)(k0 + kB) * TD + n0 + nB);
            *(float4*)&Bs[kB][nB] = bv;
        }
        __syncthreads();
#pragma unroll
        for (int kk = 0; kk < 8; kk++) {
            float a[8], b[8];
            *(float4*)&a[0] = *(const float4*)&As[kk][ty * 8];
            *(float4*)&a[4] = *(const float4*)&As[kk][ty * 8 + 4];
            *(float4*)&b[0] = *(const float4*)&Bs[kk][tx * 8];
            *(float4*)&b[4] = *(const float4*)&Bs[kk][tx * 8 + 4];
#pragma unroll
            for (int i = 0; i < 8; i++)
#pragma unroll
                for (int j = 0; j < 8; j++) acc[i][j] = fmaf(a[i], b[j], acc[i][j]);
        }
        __syncthreads();
    }
#pragma unroll
    for (int i = 0; i < 8; i++) {
        int m = m0 + ty * 8 + i;
#pragma unroll
        for (int j = 0; j < 8; j += 4) {
            int n = n0 + tx * 8 + j;
            float4 o;
            o.x = acc[i][j]; o.y = acc[i][j + 1]; o.z = acc[i][j + 2]; o.w = acc[i][j + 3];
            if (ADD_BASE) {
                float4 bb = *(const float4*)(Base + (size_t)m * TD + n);
                o.x += bb.x; o.y += bb.y; o.z += bb.z; o.w += bb.w;
            }
            *(float4*)(C + (size_t)m * TD + n) = o;
        }
    }
}

// ------- exact top-OMEGA hard threshold (radix select on |v| bits) -------
// Block of 256 threads, acc[j] holds element (tid + j*256) of the row.
// Writes dense thresholded row + compacted sparse list.  Matches reference
// semantics exactly: keep all entries with |v| >= (50th largest |v|).
__device__ __forceinline__ void select_and_emit(
    float acc[8], int b, float* __restrict__ denseOut)
{
    __shared__ unsigned s_keys[TD];
    __shared__ int s_hist[256];
    __shared__ unsigned s_prefix;
    __shared__ int s_rem;
    __shared__ int s_wc;
    const int tid = threadIdx.x;
#pragma unroll
    for (int j = 0; j < 8; j++)
        s_keys[tid + j * 256] = __float_as_uint(fabsf(acc[j]));
    if (tid == 0) { s_prefix = 0u; s_rem = KOM; s_wc = 0; }
    __syncthreads();
    for (int shift = 24; shift >= 0; shift -= 8) {
        s_hist[tid] = 0;
        __syncthreads();
        unsigned pref = s_prefix;
        unsigned maskhi = (shift == 24) ? 0u : (0xFFFFFFFFu << (shift + 8));
#pragma unroll
        for (int j = 0; j < 8; j++) {
            unsigned key = s_keys[tid + j * 256];
            if ((key & maskhi) == pref)
                atomicAdd(&s_hist[(key >> shift) & 255], 1);
        }
        __syncthreads();
        if (tid == 0) {
            int rem = s_rem; int bkt = 255;
            for (; bkt > 0; bkt--) { int c = s_hist[bkt]; if (c >= rem) break; rem -= c; }
            s_prefix = pref | ((unsigned)bkt << shift);
            s_rem = rem;
        }
        __syncthreads();
    }
    unsigned kth = s_prefix;
#pragma unroll
    for (int j = 0; j < 8; j++) {
        int i = tid + j * 256;
        float v = acc[j];
        bool keep = __float_as_uint(fabsf(v)) >= kth;
        denseOut[(size_t)b * TD + i] = keep ? v : 0.f;
        if (keep) {
            int p = atomicAdd(&s_wc, 1);
            if (p < CAP) { g_vals[b * CAP + p] = v; g_cols[b * CAP + p] = i; }
        }
    }
    __syncthreads();
    if (tid == 0) g_cnt[b] = (s_wc < CAP) ? s_wc : CAP;
}

__global__ __launch_bounds__(256) void thr_kernel(
    const float* __restrict__ T, float* __restrict__ denseOut)
{
    int b = blockIdx.x;
    float acc[8];
#pragma unroll
    for (int j = 0; j < 8; j++) acc[j] = T[(size_t)b * TD + threadIdx.x + j * 256];
    select_and_emit(acc, b, denseOut);
}

// ------- sparse apply: out[b,:] = (Base) + sum_k vals[b,k]*Mat[cols[b,k],:]
template<int DO_THR, int ADD_BASE>
__global__ __launch_bounds__(256) void sparse_apply_kernel(
    const float* __restrict__ Mat, const float* __restrict__ Base,
    float* __restrict__ denseOut)
{
    int b = blockIdx.x;
    int tid = threadIdx.x;
    __shared__ float sv[CAP]; __shared__ int sc[CAP];
    int cnt = g_cnt[b];
    if (tid < CAP) { sv[tid] = g_vals[b * CAP + tid]; sc[tid] = g_cols[b * CAP + tid]; }
    __syncthreads();
    float acc[8];
#pragma unroll
    for (int j = 0; j < 8; j++)
        acc[j] = ADD_BASE ? Base[(size_t)b * TD + tid + j * 256] : 0.f;
    for (int k = 0; k < cnt; k++) {
        float v = sv[k];
        const float* row = Mat + (size_t)sc[k] * TD;
#pragma unroll
        for (int j = 0; j < 8; j++) acc[j] = fmaf(v, row[tid + j * 256], acc[j]);
    }
    if (DO_THR) {
        select_and_emit(acc, b, denseOut);
    } else {
#pragma unroll
        for (int j = 0; j < 8; j++) denseOut[(size_t)b * TD + tid + j * 256] = acc[j];
    }
}

// ------- attention: raw scores, softmax over batch axis, weighted sum ----
__global__ __launch_bounds__(256) void att_dot_kernel(const float* __restrict__ prev)
{
    int b = blockIdx.x, p = blockIdx.y, tid = threadIdx.x;
    const float* pr = prev + ((size_t)p * NB + b) * TD;
    const float* v = g_V + (size_t)b * TD;
    float s = 0.f;
#pragma unroll
    for (int j = 0; j < 8; j++) { int d = tid + j * 256; s = fmaf(pr[d], v[d], s); }
    __shared__ float red[256];
    red[tid] = s; __syncthreads();
    for (int off = 128; off > 0; off >>= 1) {
        if (tid < off) red[tid] += red[tid + off];
        __syncthreads();
    }
    if (tid == 0) g_attraw[p * NB + b] = red[0];
}

__global__ __launch_bounds__(256) void softmax_kernel()
{
    int p = blockIdx.x, tid = threadIdx.x;
    float x[8];
#pragma unroll
    for (int j = 0; j < 8; j++) x[j] = g_attraw[p * NB + tid + j * 256];
    __shared__ float red[256];
    float m = x[0];
#pragma unroll
    for (int j = 1; j < 8; j++) m = fmaxf(m, x[j]);
    red[tid] = m; __syncthreads();
    for (int off = 128; off > 0; off >>= 1) {
        if (tid < off) red[tid] = fmaxf(red[tid], red[tid + off]);
        __syncthreads();
    }
    m = red[0]; __syncthreads();
    float s = 0.f;
#pragma unroll
    for (int j = 0; j < 8; j++) { x[j] = expf(x[j] - m); s += x[j]; }
    red[tid] = s; __syncthreads();
    for (int off = 128; off > 0; off >>= 1) {
        if (tid < off) red[tid] += red[tid + off];
        __syncthreads();
    }
    float inv = 1.f / red[0];
#pragma unroll
    for (int j = 0; j < 8; j++) g_att[p * NB + tid + j * 256] = x[j] * inv;
}

__global__ __launch_bounds__(256) void zatt_kernel(
    const float* __restrict__ prev, const float* __restrict__ lambda2)
{
    int b = blockIdx.x, tid = threadIdx.x;
    __shared__ float a[NP];
    if (tid < NP) a[tid] = g_att[tid * NB + b];
    __syncthreads();
    float l2 = *lambda2;
#pragma unroll
    for (int j = 0; j < 8; j++) {
        int d = tid + j * 256;
        float s = 0.f;
#pragma unroll
        for (int p = 0; p < NP; p++) {
            float w = prev[((size_t)p * NB + b) * TD + d];
            w = fminf(fmaxf(w, -150.f), 150.f);
            s = fmaf(w, a[p], s);
        }
        g_V[(size_t)b * TD + d] = l2 * s;   // g_V reused as z_att (v fully consumed)
    }
}

// ------- spectrum from final sparse z, then min-max normalize -----------
__global__ void zero_mD_kernel() { g_mD[threadIdx.x] = 0.f; }

__global__ void spec_kernel()
{
    int b = blockIdx.x, tid = threadIdx.x;  // 64 threads
    int cnt = g_cnt[b];
    if (tid < cnt) {
        float v = g_vals[b * CAP + tid];
        int c = g_cols[b * CAP + tid];
        atomicAdd(&g_mD[c & 1023], v * v);
    }
}

__global__ __launch_bounds__(256) void norm_kernel(float* __restrict__ out)
{
    int tid = threadIdx.x;
    float x[4];
#pragma unroll
    for (int j = 0; j < 4; j++) x[j] = g_mD[tid + j * 256];
    __shared__ float rmn[256], rmx[256];
    float mn = x[0], mx = x[0];
#pragma unroll
    for (int j = 1; j < 4; j++) { mn = fminf(mn, x[j]); mx = fmaxf(mx, x[j]); }
    rmn[tid] = mn; rmx[tid] = mx; __syncthreads();
    for (int off = 128; off > 0; off >>= 1) {
        if (tid < off) {
            rmn[tid] = fminf(rmn[tid], rmn[tid + off]);
            rmx[tid] = fmaxf(rmx[tid], rmx[tid + off]);
        }
        __syncthreads();
    }
    mn = rmn[0]; mx = rmx[0];
    float inv = 1.f / (mx - mn + 1e-8f);
#pragma unroll
    for (int j = 0; j < 4; j++) out[tid + j * 256] = (x[j] - mn) * inv;
}

// ------------------------------- driver ---------------------------------
extern "C" void kernel_launch(void* const* d_in, const int* in_sizes, int n_in,
                              void* d_out, int out_size)
{
    const float* x       = (const float*)d_in[0];  // (2048, 2048)
    const float* prev    = (const float*)d_in[1];  // (8, 2048, 2048)
    const float* Wd      = (const float*)d_in[2];  // (2048, 2048)
    const float* S       = (const float*)d_in[3];  // (2048, 2048), symmetric
    const float* lambda2 = (const float*)d_in[4];  // scalar

    float* out    = (float*)d_out;
    float* out_mD = out;           // (1024,)
    float* out_z  = out + 1024;    // (2048, 2048)

    float *pB, *pM, *pT, *pV;
    cudaGetSymbolAddress((void**)&pB, g_B);
    cudaGetSymbolAddress((void**)&pM, g_M);
    cudaGetSymbolAddress((void**)&pT, g_T);
    cudaGetSymbolAddress((void**)&pV, g_V);

    dim3 g16(16, 16);

    // B = x @ W_d^T   (1/L == 1)
    sgemm_kernel<1, 0><<<g16, 256>>>(x, Wd, nullptr, pB);
    // z1 = thr(B)
    thr_kernel<<<NB, 256>>>(pB, pT);
    // z2 = thr(B + S z1)   (S symmetric -> row gathers)
    sparse_apply_kernel<1, 1><<<NB, 256>>>(S, pB, pT);
    // M = W_d @ W_d  (for att[p,b] = prev[p,b] . (M z2)[b])
    sgemm_kernel<0, 0><<<g16, 256>>>(Wd, Wd, nullptr, pM);
    // v = M^T gather via sparse z2:  v[b,:] = sum_k val_k * M[col_k, :]
    sparse_apply_kernel<0, 0><<<NB, 256>>>(pM, nullptr, pV);
    // raw attention scores + softmax over batch axis
    att_dot_kernel<<<dim3(NB, NP), 256>>>(prev);
    softmax_kernel<<<NP, 256>>>();
    // z_att = lambda2 * sum_p clip(prev_p) * att[p,b]   -> g_V
    zatt_kernel<<<NB, 256>>>(prev, lambda2);
    // LIHT iter 1 (z_att dense): T = B + z_att @ S  (S symmetric)
    sgemm_kernel<0, 1><<<g16, 256>>>(pV, S, pB, pT);
    thr_kernel<<<NB, 256>>>(pT, pT);
    // LIHT iters 2..9 (sparse)
    for (int it = 0; it < 8; it++)
        sparse_apply_kernel<1, 1><<<NB, 256>>>(S, pB, pT);
    // LIHT iter 10: dense output straight to d_out
    sparse_apply_kernel<1, 1><<<NB, 256>>>(S, pB, out_z);
    // power spectrum + min-max normalize
    zero_mD_kernel<<<1, 1024>>>();
    spec_kernel<<<NB, 64>>>();
    norm_kernel<<<1, 256>>>(out_mD);

    (void)in_sizes; (void)n_in; (void)out_size;
}

// round 9
// speedup vs baseline: 2.1205x; 2.1205x over previous
#include <cuda_runtime.h>
#include <cuda_bf16.h>
#include <cstdint>

#define TD 2048      // D = 2*W
#define NB 2048      // BATCH
#define NP 8         // P previous windows
#define KOM 50       // OMEGA
#define CAP 64       // sparse capacity per row

// ------------------- scratch (static device globals) -------------------
__device__ float g_B[(size_t)NB * TD];
__device__ float g_M[(size_t)TD * TD];
__device__ float g_T[(size_t)NB * TD];
__device__ float g_V[(size_t)NB * TD];
__device__ __nv_bfloat16 g_wh[(size_t)TD * TD], g_wm[(size_t)TD * TD], g_wl[(size_t)TD * TD];
__device__ __nv_bfloat16 g_wth[(size_t)TD * TD], g_wtm[(size_t)TD * TD], g_wtl[(size_t)TD * TD];
__device__ float g_vals[NB * CAP];
__device__ int   g_cols[NB * CAP];
__device__ int   g_cnt[NB];
__device__ float g_attraw[NP * NB];
__device__ float g_att[NP * NB];
__device__ float g_mD[1024];

// ========== R4's proven fp32 GEMM (ascending-k FFMA chain) ==============
// C[m,n] = (ADD_BASE? Base[m,n]:0) + sum_k A[m,k]*(TRANS_B ? Bm[n,k] : Bm[k,n])
template<int TRANS_B, int ADD_BASE>
__global__ __launch_bounds__(256) void sgemm_kernel(
    const float* __restrict__ A, const float* __restrict__ Bm,
    const float* __restrict__ Base, float* __restrict__ C)
{
    __shared__ float As[8][128];
    __shared__ float Bs[8][132];
    const int tid = threadIdx.x;
    const int m0 = blockIdx.y * 128, n0 = blockIdx.x * 128;
    const int tx = tid & 15, ty = tid >> 4;
    const int rowA = tid >> 1, kA = (tid & 1) * 4;
    const int kB = tid >> 5, nB = (tid & 31) * 4;
    float acc[8][8];
#pragma unroll
    for (int i = 0; i < 8; i++)
#pragma unroll
        for (int j = 0; j < 8; j++) acc[i][j] = 0.f;

    for (int k0 = 0; k0 < TD; k0 += 8) {
        float4 av = *(const float4*)(A + (size_t)(m0 + rowA) * TD + k0 + kA);
        As[kA + 0][rowA] = av.x; As[kA + 1][rowA] = av.y;
        As[kA + 2][rowA] = av.z; As[kA + 3][rowA] = av.w;
        if (TRANS_B) {
            float4 bv = *(const float4*)(Bm + (size_t)(n0 + rowA) * TD + k0 + kA);
            Bs[kA + 0][rowA] = bv.x; Bs[kA + 1][rowA] = bv.y;
            Bs[kA + 2][rowA] = bv.z; Bs[kA + 3][rowA] = bv.w;
        } else {
            float4 bv = *(const float4*)(Bm + (size_t)(k0 + kB) * TD + n0 + nB);
            *(float4*)&Bs[kB][nB] = bv;
        }
        __syncthreads();
#pragma unroll
        for (int kk = 0; kk < 8; kk++) {
            float a[8], b[8];
            *(float4*)&a[0] = *(const float4*)&As[kk][ty * 8];
            *(float4*)&a[4] = *(const float4*)&As[kk][ty * 8 + 4];
            *(float4*)&b[0] = *(const float4*)&Bs[kk][tx * 8];
            *(float4*)&b[4] = *(const float4*)&Bs[kk][tx * 8 + 4];
#pragma unroll
            for (int i = 0; i < 8; i++)
#pragma unroll
                for (int j = 0; j < 8; j++) acc[i][j] = fmaf(a[i], b[j], acc[i][j]);
        }
        __syncthreads();
    }
#pragma unroll
    for (int i = 0; i < 8; i++) {
        int m = m0 + ty * 8 + i;
#pragma unroll
        for (int j = 0; j < 8; j += 4) {
            int n = n0 + tx * 8 + j;
            float4 o;
            o.x = acc[i][j]; o.y = acc[i][j + 1]; o.z = acc[i][j + 2]; o.w = acc[i][j + 3];
            if (ADD_BASE) {
                float4 bb = *(const float4*)(Base + (size_t)m * TD + n);
                o.x += bb.x; o.y += bb.y; o.z += bb.z; o.w += bb.w;
            }
            *(float4*)(C + (size_t)m * TD + n) = o;
        }
    }
}

// ========== tensor-core 3-split GEMM (for M only; smooth use) ===========
__device__ __forceinline__ uint32_t smem_u32(const void* p) {
    uint32_t a;
    asm("{ .reg .u64 t; cvta.to.shared.u64 t, %1; cvt.u32.u64 %0, t; }"
        : "=r"(a) : "l"(p));
    return a;
}
__device__ __forceinline__ void cp_async16(uint32_t dst, const void* src) {
    asm volatile("cp.async.cg.shared.global [%0], [%1], 16;" :: "r"(dst), "l"(src));
}
__device__ __forceinline__ void cp_commit() {
    asm volatile("cp.async.commit_group;" ::: "memory");
}
template<int N> __device__ __forceinline__ void cp_wait() {
    asm volatile("cp.async.wait_group %0;" :: "n"(N) : "memory");
}
__device__ __forceinline__ void ldsm4(uint32_t* r, uint32_t a) {
    asm volatile("ldmatrix.sync.aligned.m8n8.x4.shared.b16 {%0,%1,%2,%3}, [%4];"
        : "=r"(r[0]), "=r"(r[1]), "=r"(r[2]), "=r"(r[3]) : "r"(a));
}
__device__ __forceinline__ void mma_bf16(float* c, const uint32_t* a, const uint32_t* b) {
    asm volatile(
        "mma.sync.aligned.m16n8k16.row.col.f32.bf16.bf16.f32 "
        "{%0,%1,%2,%3}, {%4,%5,%6,%7}, {%8,%9}, {%0,%1,%2,%3};"
        : "+f"(c[0]), "+f"(c[1]), "+f"(c[2]), "+f"(c[3])
        : "r"(a[0]), "r"(a[1]), "r"(a[2]), "r"(a[3]), "r"(b[0]), "r"(b[1]));
}

__global__ __launch_bounds__(256) void split3_kernel(
    const float* __restrict__ X, __nv_bfloat16* __restrict__ H,
    __nv_bfloat16* __restrict__ M, __nv_bfloat16* __restrict__ Lo)
{
    size_t i = ((size_t)blockIdx.x * 256 + threadIdx.x) * 4;
    float4 v = *(const float4*)(X + i);
    float f[4] = {v.x, v.y, v.z, v.w};
    __nv_bfloat16 hh[4], mm[4], ll[4];
#pragma unroll
    for (int j = 0; j < 4; j++) {
        hh[j] = __float2bfloat16(f[j]);
        float r = f[j] - __bfloat162float(hh[j]);
        mm[j] = __float2bfloat16(r);
        ll[j] = __float2bfloat16(r - __bfloat162float(mm[j]));
    }
    *(uint2*)(H + i) = *(uint2*)hh;
    *(uint2*)(M + i) = *(uint2*)mm;
    *(uint2*)(Lo + i) = *(uint2*)ll;
}

__global__ void tsplit3_kernel(const float* __restrict__ X,
                               __nv_bfloat16* __restrict__ H,
                               __nv_bfloat16* __restrict__ M,
                               __nv_bfloat16* __restrict__ Lo)
{
    __shared__ float t[32][33];
    int bx = blockIdx.x * 32, by = blockIdx.y * 32;
    int tx = threadIdx.x, ty = threadIdx.y;   // (32, 8)
#pragma unroll
    for (int r = 0; r < 32; r += 8)
        t[ty + r][tx] = X[(size_t)(by + ty + r) * TD + bx + tx];
    __syncthreads();
#pragma unroll
    for (int r = 0; r < 32; r += 8) {
        float v = t[tx][ty + r];
        size_t o = (size_t)(bx + ty + r) * TD + by + tx;
        __nv_bfloat16 h = __float2bfloat16(v);
        float rr = v - __bfloat162float(h);
        __nv_bfloat16 m = __float2bfloat16(rr);
        H[o] = h; M[o] = m;
        Lo[o] = __float2bfloat16(rr - __bfloat162float(m));
    }
}

template<int SPLITS>
__device__ __forceinline__ void gemm_issue_stage(
    uint32_t dbase, int tid, int k0,
    const __nv_bfloat16* const* srcs, int m0, int n0)
{
#pragma unroll
    for (int op = 0; op < 2 * SPLITS; op++) {
        const __nv_bfloat16* src = srcs[op];
        const int r0 = (op < SPLITS) ? m0 : n0;
#pragma unroll
        for (int i = 0; i < 4; i++) {
            int idx = tid + i * 256;
            int row = idx >> 3, ch = idx & 7;
            uint32_t dst = dbase + op * 16384 + (uint32_t)(row << 7)
                         + (((uint32_t)(ch << 4)) ^ ((uint32_t)((row & 7) << 4)));
            cp_async16(dst, src + (size_t)(r0 + row) * TD + k0 + ch * 8);
        }
    }
    cp_commit();
}

template<int SPLITS>
__global__ __launch_bounds__(256, 1) void mma_gemm_kernel(
    const __nv_bfloat16* __restrict__ A0, const __nv_bfloat16* __restrict__ A1,
    const __nv_bfloat16* __restrict__ A2,
    const __nv_bfloat16* __restrict__ B0, const __nv_bfloat16* __restrict__ B1,
    const __nv_bfloat16* __restrict__ B2,
    float* __restrict__ C)
{
    extern __shared__ char smem[];
    const uint32_t sb = smem_u32(smem);
    const uint32_t STG = SPLITS * 2 * 16384;
    const int tid = threadIdx.x;
    const int wid = tid >> 5, lane = tid & 31;
    const int wm = wid >> 2, wn = wid & 3;
    const int m0 = blockIdx.y * 128, n0 = blockIdx.x * 128;

    const __nv_bfloat16* srcs[6] = {A0, A1, A2, B0, B1, B2};
    const __nv_bfloat16* s6[2 * SPLITS];
#pragma unroll
    for (int i = 0; i < SPLITS; i++) { s6[i] = srcs[i]; s6[SPLITS + i] = srcs[3 + i]; }

    float acc[4][4][4];
#pragma unroll
    for (int i = 0; i < 4; i++)
#pragma unroll
        for (int j = 0; j < 4; j++)
#pragma unroll
            for (int q = 0; q < 4; q++) acc[i][j][q] = 0.f;

    gemm_issue_stage<SPLITS>(sb, tid, 0, s6, m0, n0);

    for (int c = 0; c < 32; c++) {
        if (c + 1 < 32) {
            gemm_issue_stage<SPLITS>(sb + ((c + 1) & 1) * STG, tid, (c + 1) * 64,
                                     s6, m0, n0);
            cp_wait<1>();
        } else {
            cp_wait<0>();
        }
        __syncthreads();
        const uint32_t st = sb + (c & 1) * STG;
#pragma unroll
        for (int ks = 0; ks < 4; ks++) {
            uint32_t af[SPLITS][4][4], bf[SPLITS][2][4];
#pragma unroll
            for (int mt = 0; mt < 4; mt++) {
                int arow = wm * 64 + mt * 16 + (lane & 15);
                int akc = ks * 2 + (lane >> 4);
                uint32_t off = (uint32_t)(arow << 7)
                             + (((uint32_t)(akc << 4)) ^ ((uint32_t)((arow & 7) << 4)));
#pragma unroll
                for (int s = 0; s < SPLITS; s++)
                    ldsm4(af[s][mt], st + s * 16384 + off);
            }
#pragma unroll
            for (int np = 0; np < 2; np++) {
                int mtx = lane >> 3;
                int brow = wn * 32 + np * 16 + (mtx >> 1) * 8 + (lane & 7);
                int bkc = ks * 2 + (mtx & 1);
                uint32_t off = (uint32_t)(brow << 7)
                             + (((uint32_t)(bkc << 4)) ^ ((uint32_t)((brow & 7) << 4)));
#pragma unroll
                for (int s = 0; s < SPLITS; s++)
                    ldsm4(bf[s][np], st + (SPLITS + s) * 16384 + off);
            }
#pragma unroll
            for (int mt = 0; mt < 4; mt++)
#pragma unroll
                for (int nt = 0; nt < 4; nt++) {
#pragma unroll
                    for (int i = 0; i < SPLITS; i++)
#pragma unroll
                        for (int j = 0; j < SPLITS; j++)
                            if (i + j < SPLITS)
                                mma_bf16(acc[mt][nt], af[i][mt],
                                         &bf[j][nt >> 1][(nt & 1) * 2]);
                }
        }
        __syncthreads();
    }
#pragma unroll
    for (int mt = 0; mt < 4; mt++) {
        int mrow = m0 + wm * 64 + mt * 16 + (lane >> 2);
#pragma unroll
        for (int nt = 0; nt < 4; nt++) {
            int n = n0 + wn * 32 + nt * 8 + (lane & 3) * 2;
            *(float2*)(C + (size_t)mrow * TD + n) =
                make_float2(acc[mt][nt][0], acc[mt][nt][1]);
            *(float2*)(C + (size_t)(mrow + 8) * TD + n) =
                make_float2(acc[mt][nt][2], acc[mt][nt][3]);
        }
    }
}

// ========== exact top-OMEGA select: radix + scan, sorted emission ========
// 256 threads; acc[j] = value at column tid*8+j.  On return the smem list
// sv/sc holds kept (val,col) sorted ASCENDING by column, s_scnt = count,
// s_prefix = kth key.  Ends with a __syncthreads.
struct SelSmem {
    float sv[CAP];
    int   sc[CAP];
    int   hist[256];
    int   wsum[8];
    int   woff[8];
    int   wsfx[8];
    unsigned prefix;
    int   rem;
    int   scnt;
};

__device__ __forceinline__ void select_sorted(const float acc[8], SelSmem& S)
{
    const int tid = threadIdx.x;
    const int lane = tid & 31, w = tid >> 5;
    unsigned key[8];
#pragma unroll
    for (int j = 0; j < 8; j++) key[j] = __float_as_uint(fabsf(acc[j]));
    if (tid == 0) { S.prefix = 0u; S.rem = KOM; }
    __syncthreads();
#pragma unroll
    for (int shift = 24; shift >= 0; shift -= 8) {
        S.hist[tid] = 0;
        __syncthreads();
        unsigned pref = S.prefix;
        int rem = S.rem;
        unsigned maskhi = (shift == 24) ? 0u : (0xFFFFFFFFu << (shift + 8));
#pragma unroll
        for (int j = 0; j < 8; j++)
            if ((key[j] & maskhi) == pref)
                atomicAdd(&S.hist[(key[j] >> shift) & 255], 1);
        __syncthreads();
        int h = S.hist[tid];
        int s = h;
#pragma unroll
        for (int d = 1; d < 32; d <<= 1) {
            int t = __shfl_down_sync(0xFFFFFFFFu, s, d);
            if (lane + d < 32) s += t;
        }
        if (lane == 0) S.wsfx[w] = s;
        __syncthreads();
        int above = 0;
        for (int ww = w + 1; ww < 8; ww++) above += S.wsfx[ww];
        int stot = s + above;
        bool hit = (stot >= rem) && (stot - h < rem);
        __syncthreads();
        if (hit) {
            S.prefix = pref | ((unsigned)tid << shift);
            S.rem = rem - (stot - h);
        }
        __syncthreads();
    }
    unsigned kth = S.prefix;
    // rank-by-scan compaction (column-sorted by construction)
    int c = 0;
    bool keep[8];
#pragma unroll
    for (int j = 0; j < 8; j++) { keep[j] = key[j] >= kth; c += keep[j] ? 1 : 0; }
    int inc = c;
#pragma unroll
    for (int d = 1; d < 32; d <<= 1) {
        int t = __shfl_up_sync(0xFFFFFFFFu, inc, d);
        if (lane >= d) inc += t;
    }
    if (lane == 31) S.wsum[w] = inc;
    __syncthreads();
    if (tid == 0) {
        int run = 0;
#pragma unroll
        for (int ww = 0; ww < 8; ww++) { S.woff[ww] = run; run += S.wsum[ww]; }
        S.scnt = (run < CAP) ? run : CAP;
    }
    __syncthreads();
    int pos = S.woff[w] + inc - c;
#pragma unroll
    for (int j = 0; j < 8; j++) {
        if (keep[j] && pos < CAP) {
            S.sv[pos] = acc[j];
            S.sc[pos] = tid * 8 + j;
            pos++;
        }
    }
    __syncthreads();
}

// gather acc = sum_k sv[k]*Mat[sc[k], c0..], ascending column order, from 0
__device__ __forceinline__ void gather_rows(
    const float* __restrict__ Mat, const SelSmem& S, int c0, float acc[8])
{
#pragma unroll
    for (int j = 0; j < 8; j++) acc[j] = 0.f;
    int cnt = S.scnt;
    for (int k = 0; k < cnt; k++) {
        float v = S.sv[k];
        const float* row = Mat + (size_t)S.sc[k] * TD + c0;
        float4 r0 = *(const float4*)row;
        float4 r1 = *(const float4*)(row + 4);
        acc[0] = fmaf(v, r0.x, acc[0]); acc[1] = fmaf(v, r0.y, acc[1]);
        acc[2] = fmaf(v, r0.z, acc[2]); acc[3] = fmaf(v, r0.w, acc[3]);
        acc[4] = fmaf(v, r1.x, acc[4]); acc[5] = fmaf(v, r1.y, acc[5]);
        acc[6] = fmaf(v, r1.z, acc[6]); acc[7] = fmaf(v, r1.w, acc[7]);
    }
}

// ---- z1 = thr(B); z2 = thr(B + S z1); emit z2 list to global ----------
__global__ __launch_bounds__(256) void z1z2_kernel(const float* __restrict__ Smat)
{
    __shared__ SelSmem SS;
    int b = blockIdx.x, tid = threadIdx.x;
    const int c0 = tid * 8;
    float b8[8];
    const float* bp = g_B + (size_t)b * TD + c0;
    *(float4*)&b8[0] = *(const float4*)bp;
    *(float4*)&b8[4] = *(const float4*)(bp + 4);
    select_sorted(b8, SS);                       // z1
    float acc[8];
    gather_rows(Smat, SS, c0, acc);              // S z1 (ascending cols, from 0)
#pragma unroll
    for (int j = 0; j < 8; j++) acc[j] += b8[j]; // + B last (matches ref order)
    __syncthreads();
    select_sorted(acc, SS);                      // z2
    for (int i = tid; i < SS.scnt; i += 256) {
        g_vals[b * CAP + i] = SS.sv[i];
        g_cols[b * CAP + i] = SS.sc[i];
    }
    if (tid == 0) g_cnt[b] = SS.scnt;
}

// ---- thr on dense T (after z_att GEMM), emit list to global -----------
__global__ __launch_bounds__(256) void thr_kernel(const float* __restrict__ T)
{
    __shared__ SelSmem SS;
    int b = blockIdx.x, tid = threadIdx.x;
    float acc[8];
    const float* tp = T + (size_t)b * TD + tid * 8;
    *(float4*)&acc[0] = *(const float4*)tp;
    *(float4*)&acc[4] = *(const float4*)(tp + 4);
    select_sorted(acc, SS);
    for (int i = tid; i < SS.scnt; i += 256) {
        g_vals[b * CAP + i] = SS.sv[i];
        g_cols[b * CAP + i] = SS.sc[i];
    }
    if (tid == 0) g_cnt[b] = SS.scnt;
}

// ---- v[b,:] = sum_k val_k * M[col_k,:]  (smooth use; order free) ------
__global__ __launch_bounds__(256) void vapply_kernel(const float* __restrict__ Mat)
{
    __shared__ float sv[CAP]; __shared__ int sc[CAP];
    int b = blockIdx.x, tid = threadIdx.x;
    int cnt = g_cnt[b];
    if (tid < CAP) { sv[tid] = g_vals[b * CAP + tid]; sc[tid] = g_cols[b * CAP + tid]; }
    __syncthreads();
    const int c0 = tid * 8;
    float acc[8];
#pragma unroll
    for (int j = 0; j < 8; j++) acc[j] = 0.f;
    for (int k = 0; k < cnt; k++) {
        float v = sv[k];
        const float* row = Mat + (size_t)sc[k] * TD + c0;
        float4 r0 = *(const float4*)row;
        float4 r1 = *(const float4*)(row + 4);
        acc[0] = fmaf(v, r0.x, acc[0]); acc[1] = fmaf(v, r0.y, acc[1]);
        acc[2] = fmaf(v, r0.z, acc[2]); acc[3] = fmaf(v, r0.w, acc[3]);
        acc[4] = fmaf(v, r1.x, acc[4]); acc[5] = fmaf(v, r1.y, acc[5]);
        acc[6] = fmaf(v, r1.z, acc[6]); acc[7] = fmaf(v, r1.w, acc[7]);
    }
    float* dp = g_V + (size_t)b * TD + c0;
    *(float4*)dp = *(float4*)&acc[0];
    *(float4*)(dp + 4) = *(float4*)&acc[4];
}

// ---- fused LIHT: 9 iterations + dense output + spectrum ---------------
__global__ __launch_bounds__(256) void liht_kernel(
    const float* __restrict__ Smat, float* __restrict__ out_z)
{
    __shared__ SelSmem SS;
    int b = blockIdx.x, tid = threadIdx.x;
    const int c0 = tid * 8;
    float b8[8];
    const float* bp = g_B + (size_t)b * TD + c0;
    *(float4*)&b8[0] = *(const float4*)bp;
    *(float4*)&b8[4] = *(const float4*)(bp + 4);
    // init list from global (sorted, produced by thr_kernel)
    int cnt = g_cnt[b];
    if (tid < CAP) {
        SS.sv[tid] = g_vals[b * CAP + tid];
        SS.sc[tid] = g_cols[b * CAP + tid];
    }
    if (tid == 0) SS.scnt = cnt;
    __syncthreads();

    float acc[8];
    for (int it = 0; it < 9; it++) {
        gather_rows(Smat, SS, c0, acc);
#pragma unroll
        for (int j = 0; j < 8; j++) acc[j] += b8[j];
        __syncthreads();
        select_sorted(acc, SS);
    }
    // final: dense row + spectrum
    unsigned kth = SS.prefix;
    float o[8];
#pragma unroll
    for (int j = 0; j < 8; j++) {
        bool keep = __float_as_uint(fabsf(acc[j])) >= kth;
        o[j] = keep ? acc[j] : 0.f;
        if (keep) atomicAdd(&g_mD[(c0 + j) & 1023], acc[j] * acc[j]);
    }
    float* dp = out_z + (size_t)b * TD + c0;
    *(float4*)dp = *(float4*)&o[0];
    *(float4*)(dp + 4) = *(float4*)&o[4];
}

// ------- attention: raw scores, softmax over batch axis, weighted sum ----
__global__ __launch_bounds__(256) void att_dot_kernel(const float* __restrict__ prev)
{
    int b = blockIdx.x, p = blockIdx.y, tid = threadIdx.x;
    const float* pr = prev + ((size_t)p * NB + b) * TD + tid * 8;
    const float* v = g_V + (size_t)b * TD + tid * 8;
    float4 a0 = *(const float4*)pr, a1 = *(const float4*)(pr + 4);
    float4 b0 = *(const float4*)v, b1 = *(const float4*)(v + 4);
    float s = a0.x * b0.x + a0.y * b0.y + a0.z * b0.z + a0.w * b0.w
            + a1.x * b1.x + a1.y * b1.y + a1.z * b1.z + a1.w * b1.w;
    __shared__ float red[256];
    red[tid] = s; __syncthreads();
    for (int off = 128; off > 0; off >>= 1) {
        if (tid < off) red[tid] += red[tid + off];
        __syncthreads();
    }
    if (tid == 0) g_attraw[p * NB + b] = red[0];
}

__global__ __launch_bounds__(256) void softmax_kernel()
{
    int p = blockIdx.x, tid = threadIdx.x;
    float x[8];
#pragma unroll
    for (int j = 0; j < 8; j++) x[j] = g_attraw[p * NB + tid + j * 256];
    __shared__ float red[256];
    float m = x[0];
#pragma unroll
    for (int j = 1; j < 8; j++) m = fmaxf(m, x[j]);
    red[tid] = m; __syncthreads();
    for (int off = 128; off > 0; off >>= 1) {
        if (tid < off) red[tid] = fmaxf(red[tid], red[tid + off]);
        __syncthreads();
    }
    m = red[0]; __syncthreads();
    float s = 0.f;
#pragma unroll
    for (int j = 0; j < 8; j++) { x[j] = expf(x[j] - m); s += x[j]; }
    red[tid] = s; __syncthreads();
    for (int off = 128; off > 0; off >>= 1) {
        if (tid < off) red[tid] += red[tid + off];
        __syncthreads();
    }
    float inv = 1.f / red[0];
#pragma unroll
    for (int j = 0; j < 8; j++) g_att[p * NB + tid + j * 256] = x[j] * inv;
}

__global__ __launch_bounds__(256) void zatt_kernel(
    const float* __restrict__ prev, const float* __restrict__ lambda2)
{
    int b = blockIdx.x, tid = threadIdx.x;
    __shared__ float a[NP];
    if (tid < NP) a[tid] = g_att[tid * NB + b];
    __syncthreads();
    float l2 = *lambda2;
#pragma unroll
    for (int j = 0; j < 8; j++) {
        int d = tid + j * 256;
        float s = 0.f;
#pragma unroll
        for (int p = 0; p < NP; p++) {
            float w = prev[((size_t)p * NB + b) * TD + d];
            w = fminf(fmaxf(w, -150.f), 150.f);
            s = fmaf(w, a[p], s);
        }
        g_V[(size_t)b * TD + d] = l2 * s;    // v consumed; reuse as z_att
    }
}

// ------- spectrum normalize -----------------------------------------
__global__ void zero_mD_kernel() { g_mD[threadIdx.x] = 0.f; }

__global__ __launch_bounds__(256) void norm_kernel(float* __restrict__ out)
{
    int tid = threadIdx.x;
    float x[4];
#pragma unroll
    for (int j = 0; j < 4; j++) x[j] = g_mD[tid + j * 256];
    __shared__ float rmn[256], rmx[256];
    float mn = x[0], mx = x[0];
#pragma unroll
    for (int j = 1; j < 4; j++) { mn = fminf(mn, x[j]); mx = fmaxf(mx, x[j]); }
    rmn[tid] = mn; rmx[tid] = mx; __syncthreads();
    for (int off = 128; off > 0; off >>= 1) {
        if (tid < off) {
            rmn[tid] = fminf(rmn[tid], rmn[tid + off]);
            rmx[tid] = fmaxf(rmx[tid], rmx[tid + off]);
        }
        __syncthreads();
    }
    mn = rmn[0]; mx = rmx[0];
    float inv = 1.f / (mx - mn + 1e-8f);
#pragma unroll
    for (int j = 0; j < 4; j++) out[tid + j * 256] = (x[j] - mn) * inv;
}

// ------------------------------- driver ---------------------------------
extern "C" void kernel_launch(void* const* d_in, const int* in_sizes, int n_in,
                              void* d_out, int out_size)
{
    const float* x       = (const float*)d_in[0];  // (2048, 2048)
    const float* prev    = (const float*)d_in[1];  // (8, 2048, 2048)
    const float* Wd      = (const float*)d_in[2];  // (2048, 2048)
    const float* S       = (const float*)d_in[3];  // (2048, 2048), symmetric
    const float* lambda2 = (const float*)d_in[4];  // scalar

    float* out    = (float*)d_out;
    float* out_mD = out;           // (1024,)
    float* out_z  = out + 1024;    // (2048, 2048)

    float *pB, *pM, *pT, *pV;
    __nv_bfloat16 *wh, *wm, *wl, *wth, *wtm, *wtl;
    cudaGetSymbolAddress((void**)&pB, g_B);
    cudaGetSymbolAddress((void**)&pM, g_M);
    cudaGetSymbolAddress((void**)&pT, g_T);
    cudaGetSymbolAddress((void**)&pV, g_V);
    cudaGetSymbolAddress((void**)&wh, g_wh);   cudaGetSymbolAddress((void**)&wm, g_wm);
    cudaGetSymbolAddress((void**)&wl, g_wl);
    cudaGetSymbolAddress((void**)&wth, g_wth); cudaGetSymbolAddress((void**)&wtm, g_wtm);
    cudaGetSymbolAddress((void**)&wtl, g_wtl);

    const int SMEM3 = 3 * 2 * 16384 * 2;   // 196608
    cudaFuncSetAttribute(mma_gemm_kernel<3>,
                         cudaFuncAttributeMaxDynamicSharedMemorySize, SMEM3);

    const int SPLIT_BLKS = (int)(((size_t)TD * TD) / 1024);
    dim3 g16(16, 16);

    // B = x @ Wd^T  (fp32 ascending-k chain: selection-critical)
    sgemm_kernel<1, 0><<<g16, 256>>>(x, Wd, nullptr, pB);
    // z1, z2 fused (sorted sparse sums; +B last to match ref rounding)
    z1z2_kernel<<<NB, 256>>>(S);
    // M = Wd @ Wd  (tensor 3-split; feeds softmax only)
    split3_kernel<<<SPLIT_BLKS, 256>>>(Wd, wh, wm, wl);
    tsplit3_kernel<<<dim3(64, 64), dim3(32, 8)>>>(Wd, wth, wtm, wtl);
    mma_gemm_kernel<3><<<g16, 256, SMEM3>>>(wh, wm, wl, wth, wtm, wtl, pM);
    // v = sparse(z2) . M rows
    vapply_kernel<<<NB, 256>>>(pM);
    // attention + z_att
    att_dot_kernel<<<dim3(NB, NP), 256>>>(prev);
    softmax_kernel<<<NP, 256>>>();
    zatt_kernel<<<NB, 256>>>(prev, lambda2);
    // LIHT iter 1 (dense): T = z_att @ S + B  (fp32 chain, +B last)
    sgemm_kernel<0, 1><<<g16, 256>>>(pV, S, pB, pT);
    thr_kernel<<<NB, 256>>>(pT);
    // LIHT iters 2..10 fused + spectrum + dense out
    zero_mD_kernel<<<1, 1024>>>();
    liht_kernel<<<NB, 256>>>(S, out_z);
    norm_kernel<<<1, 256>>>(out_mD);

    (void)in_sizes; (void)n_in; (void)out_size;
}

// round 12
// speedup vs baseline: 2.2422x; 1.0574x over previous
#include <cuda_runtime.h>
#include <cuda_bf16.h>
#include <cstdint>

#define TD 2048      // D = 2*W
#define NB 2048      // BATCH
#define NP 8         // P previous windows
#define KOM 50       // OMEGA
#define CAP 64       // sparse capacity per row

// ------------------- scratch (static device globals) -------------------
__device__ float g_B[(size_t)NB * TD];
__device__ float g_M[(size_t)TD * TD];
__device__ float g_T[(size_t)NB * TD];
__device__ float g_V[(size_t)NB * TD];
__device__ __nv_bfloat16 g_wh[(size_t)TD * TD], g_wm[(size_t)TD * TD], g_wl[(size_t)TD * TD];
__device__ __nv_bfloat16 g_wth[(size_t)TD * TD], g_wtm[(size_t)TD * TD], g_wtl[(size_t)TD * TD];
__device__ float g_vals[NB * CAP];
__device__ int   g_cols[NB * CAP];
__device__ int   g_cnt[NB];
__device__ float g_attraw[NP * NB];
__device__ float g_att[NP * NB];
__device__ float g_mD[1024];

// ========== fp32 GEMM v2: 16x8 rtile, 128 thr, BK=8, double-buffered =====
// C[m,n] = (ADD_BASE? Base[m,n]:0) + sum_k A[m,k]*(TRANS_B ? Bm[n,k] : Bm[k,n])
// Ascending-k single-accumulator fmaf chain per element (bitwise == R4 sgemm).
template<int TRANS_B, int ADD_BASE>
__global__ __launch_bounds__(128, 2) void sgemm2_kernel(
    const float* __restrict__ A, const float* __restrict__ Bm,
    const float* __restrict__ Base, float* __restrict__ C)
{
    __shared__ float As[2][8][132];
    __shared__ float Bs[2][8][132];
    const int tid = threadIdx.x;
    const int tx = tid & 15, ty = tid >> 4;          // tx: n-group, ty: m-group
    const int m0 = blockIdx.y * 128, n0 = blockIdx.x * 128;

    // staging index precompute (2 float4 per operand per thread)
    const int idx0 = tid, idx1 = tid + 128;
    const int am0 = idx0 >> 1, akc0 = (idx0 & 1) * 4;
    const int am1 = idx1 >> 1, akc1 = (idx1 & 1) * 4;
    const int bk0 = idx0 >> 5, bnc0 = (idx0 & 31) * 4;   // non-trans B
    const int bk1 = idx1 >> 5, bnc1 = (idx1 & 31) * 4;

    float acc[16][8];
#pragma unroll
    for (int i = 0; i < 16; i++)
#pragma unroll
        for (int j = 0; j < 8; j++) acc[i][j] = 0.f;

    float4 ar0, ar1, br0, br1;
    // prologue: load k-block 0
    ar0 = *(const float4*)(A + (size_t)(m0 + am0) * TD + akc0);
    ar1 = *(const float4*)(A + (size_t)(m0 + am1) * TD + akc1);
    if (TRANS_B) {
        br0 = *(const float4*)(Bm + (size_t)(n0 + am0) * TD + akc0);
        br1 = *(const float4*)(Bm + (size_t)(n0 + am1) * TD + akc1);
    } else {
        br0 = *(const float4*)(Bm + (size_t)bk0 * TD + n0 + bnc0);
        br1 = *(const float4*)(Bm + (size_t)bk1 * TD + n0 + bnc1);
    }
    // store stage 0
    {
        As[0][akc0 + 0][am0] = ar0.x; As[0][akc0 + 1][am0] = ar0.y;
        As[0][akc0 + 2][am0] = ar0.z; As[0][akc0 + 3][am0] = ar0.w;
        As[0][akc1 + 0][am1] = ar1.x; As[0][akc1 + 1][am1] = ar1.y;
        As[0][akc1 + 2][am1] = ar1.z; As[0][akc1 + 3][am1] = ar1.w;
        if (TRANS_B) {
            Bs[0][akc0 + 0][am0] = br0.x; Bs[0][akc0 + 1][am0] = br0.y;
            Bs[0][akc0 + 2][am0] = br0.z; Bs[0][akc0 + 3][am0] = br0.w;
            Bs[0][akc1 + 0][am1] = br1.x; Bs[0][akc1 + 1][am1] = br1.y;
            Bs[0][akc1 + 2][am1] = br1.z; Bs[0][akc1 + 3][am1] = br1.w;
        } else {
            *(float4*)&Bs[0][bk0][bnc0] = br0;
            *(float4*)&Bs[0][bk1][bnc1] = br1;
        }
    }
    __syncthreads();

    for (int kb = 0; kb < 256; kb++) {
        const int cur = kb & 1;
        if (kb < 255) {
            const int k0n = (kb + 1) * 8;
            ar0 = *(const float4*)(A + (size_t)(m0 + am0) * TD + k0n + akc0);
            ar1 = *(const float4*)(A + (size_t)(m0 + am1) * TD + k0n + akc1);
            if (TRANS_B) {
                br0 = *(const float4*)(Bm + (size_t)(n0 + am0) * TD + k0n + akc0);
                br1 = *(const float4*)(Bm + (size_t)(n0 + am1) * TD + k0n + akc1);
            } else {
                br0 = *(const float4*)(Bm + (size_t)(k0n + bk0) * TD + n0 + bnc0);
                br1 = *(const float4*)(Bm + (size_t)(k0n + bk1) * TD + n0 + bnc1);
            }
        }
#pragma unroll
        for (int kk = 0; kk < 8; kk++) {
            float a[16], b[8];
            *(float4*)&a[0]  = *(const float4*)&As[cur][kk][ty * 16 + 0];
            *(float4*)&a[4]  = *(const float4*)&As[cur][kk][ty * 16 + 4];
            *(float4*)&a[8]  = *(const float4*)&As[cur][kk][ty * 16 + 8];
            *(float4*)&a[12] = *(const float4*)&As[cur][kk][ty * 16 + 12];
            *(float4*)&b[0]  = *(const float4*)&Bs[cur][kk][tx * 8 + 0];
            *(float4*)&b[4]  = *(const float4*)&Bs[cur][kk][tx * 8 + 4];
#pragma unroll
            for (int i = 0; i < 16; i++)
#pragma unroll
                for (int j = 0; j < 8; j++) acc[i][j] = fmaf(a[i], b[j], acc[i][j]);
        }
        if (kb < 255) {
            const int nb = cur ^ 1;
            As[nb][akc0 + 0][am0] = ar0.x; As[nb][akc0 + 1][am0] = ar0.y;
            As[nb][akc0 + 2][am0] = ar0.z; As[nb][akc0 + 3][am0] = ar0.w;
            As[nb][akc1 + 0][am1] = ar1.x; As[nb][akc1 + 1][am1] = ar1.y;
            As[nb][akc1 + 2][am1] = ar1.z; As[nb][akc1 + 3][am1] = ar1.w;
            if (TRANS_B) {
                Bs[nb][akc0 + 0][am0] = br0.x; Bs[nb][akc0 + 1][am0] = br0.y;
                Bs[nb][akc0 + 2][am0] = br0.z; Bs[nb][akc0 + 3][am0] = br0.w;
                Bs[nb][akc1 + 0][am1] = br1.x; Bs[nb][akc1 + 1][am1] = br1.y;
                Bs[nb][akc1 + 2][am1] = br1.z; Bs[nb][akc1 + 3][am1] = br1.w;
            } else {
                *(float4*)&Bs[nb][bk0][bnc0] = br0;
                *(float4*)&Bs[nb][bk1][bnc1] = br1;
            }
            __syncthreads();
        }
    }

#pragma unroll
    for (int i = 0; i < 16; i++) {
        int m = m0 + ty * 16 + i;
#pragma unroll
        for (int j = 0; j < 8; j += 4) {
            int n = n0 + tx * 8 + j;
            float4 o;
            o.x = acc[i][j]; o.y = acc[i][j + 1]; o.z = acc[i][j + 2]; o.w = acc[i][j + 3];
            if (ADD_BASE) {
                float4 bb = *(const float4*)(Base + (size_t)m * TD + n);
                o.x += bb.x; o.y += bb.y; o.z += bb.z; o.w += bb.w;
            }
            *(float4*)(C + (size_t)m * TD + n) = o;
        }
    }
}

// ========== tensor-core 3-split GEMM (for M only; smooth use) ===========
__device__ __forceinline__ uint32_t smem_u32(const void* p) {
    uint32_t a;
    asm("{ .reg .u64 t; cvta.to.shared.u64 t, %1; cvt.u32.u64 %0, t; }"
        : "=r"(a) : "l"(p));
    return a;
}
__device__ __forceinline__ void cp_async16(uint32_t dst, const void* src) {
    asm volatile("cp.async.cg.shared.global [%0], [%1], 16;" :: "r"(dst), "l"(src));
}
__device__ __forceinline__ void cp_commit() {
    asm volatile("cp.async.commit_group;" ::: "memory");
}
template<int N> __device__ __forceinline__ void cp_wait() {
    asm volatile("cp.async.wait_group %0;" :: "n"(N) : "memory");
}
__device__ __forceinline__ void ldsm4(uint32_t* r, uint32_t a) {
    asm volatile("ldmatrix.sync.aligned.m8n8.x4.shared.b16 {%0,%1,%2,%3}, [%4];"
        : "=r"(r[0]), "=r"(r[1]), "=r"(r[2]), "=r"(r[3]) : "r"(a));
}
__device__ __forceinline__ void mma_bf16(float* c, const uint32_t* a, const uint32_t* b) {
    asm volatile(
        "mma.sync.aligned.m16n8k16.row.col.f32.bf16.bf16.f32 "
        "{%0,%1,%2,%3}, {%4,%5,%6,%7}, {%8,%9}, {%0,%1,%2,%3};"
        : "+f"(c[0]), "+f"(c[1]), "+f"(c[2]), "+f"(c[3])
        : "r"(a[0]), "r"(a[1]), "r"(a[2]), "r"(a[3]), "r"(b[0]), "r"(b[1]));
}

__global__ __launch_bounds__(256) void split3_kernel(
    const float* __restrict__ X, __nv_bfloat16* __restrict__ H,
    __nv_bfloat16* __restrict__ M, __nv_bfloat16* __restrict__ Lo)
{
    size_t i = ((size_t)blockIdx.x * 256 + threadIdx.x) * 4;
    float4 v = *(const float4*)(X + i);
    float f[4] = {v.x, v.y, v.z, v.w};
    __nv_bfloat16 hh[4], mm[4], ll[4];
#pragma unroll
    for (int j = 0; j < 4; j++) {
        hh[j] = __float2bfloat16(f[j]);
        float r = f[j] - __bfloat162float(hh[j]);
        mm[j] = __float2bfloat16(r);
        ll[j] = __float2bfloat16(r - __bfloat162float(mm[j]));
    }
    *(uint2*)(H + i) = *(uint2*)hh;
    *(uint2*)(M + i) = *(uint2*)mm;
    *(uint2*)(Lo + i) = *(uint2*)ll;
}

__global__ void tsplit3_kernel(const float* __restrict__ X,
                               __nv_bfloat16* __restrict__ H,
                               __nv_bfloat16* __restrict__ M,
                               __nv_bfloat16* __restrict__ Lo)
{
    __shared__ float t[32][33];
    int bx = blockIdx.x * 32, by = blockIdx.y * 32;
    int tx = threadIdx.x, ty = threadIdx.y;   // (32, 8)
#pragma unroll
    for (int r = 0; r < 32; r += 8)
        t[ty + r][tx] = X[(size_t)(by + ty + r) * TD + bx + tx];
    __syncthreads();
#pragma unroll
    for (int r = 0; r < 32; r += 8) {
        float v = t[tx][ty + r];
        size_t o = (size_t)(bx + ty + r) * TD + by + tx;
        __nv_bfloat16 h = __float2bfloat16(v);
        float rr = v - __bfloat162float(h);
        __nv_bfloat16 m = __float2bfloat16(rr);
        H[o] = h; M[o] = m;
        Lo[o] = __float2bfloat16(rr - __bfloat162float(m));
    }
}

template<int SPLITS>
__device__ __forceinline__ void gemm_issue_stage(
    uint32_t dbase, int tid, int k0,
    const __nv_bfloat16* const* srcs, int m0, int n0)
{
#pragma unroll
    for (int op = 0; op < 2 * SPLITS; op++) {
        const __nv_bfloat16* src = srcs[op];
        const int r0 = (op < SPLITS) ? m0 : n0;
#pragma unroll
        for (int i = 0; i < 4; i++) {
            int idx = tid + i * 256;
            int row = idx >> 3, ch = idx & 7;
            uint32_t dst = dbase + op * 16384 + (uint32_t)(row << 7)
                         + (((uint32_t)(ch << 4)) ^ ((uint32_t)((row & 7) << 4)));
            cp_async16(dst, src + (size_t)(r0 + row) * TD + k0 + ch * 8);
        }
    }
    cp_commit();
}

template<int SPLITS>
__global__ __launch_bounds__(256, 1) void mma_gemm_kernel(
    const __nv_bfloat16* __restrict__ A0, const __nv_bfloat16* __restrict__ A1,
    const __nv_bfloat16* __restrict__ A2,
    const __nv_bfloat16* __restrict__ B0, const __nv_bfloat16* __restrict__ B1,
    const __nv_bfloat16* __restrict__ B2,
    float* __restrict__ C)
{
    extern __shared__ char smem[];
    const uint32_t sb = smem_u32(smem);
    const uint32_t STG = SPLITS * 2 * 16384;
    const int tid = threadIdx.x;
    const int wid = tid >> 5, lane = tid & 31;
    const int wm = wid >> 2, wn = wid & 3;
    const int m0 = blockIdx.y * 128, n0 = blockIdx.x * 128;

    const __nv_bfloat16* srcs[6] = {A0, A1, A2, B0, B1, B2};
    const __nv_bfloat16* s6[2 * SPLITS];
#pragma unroll
    for (int i = 0; i < SPLITS; i++) { s6[i] = srcs[i]; s6[SPLITS + i] = srcs[3 + i]; }

    float acc[4][4][4];
#pragma unroll
    for (int i = 0; i < 4; i++)
#pragma unroll
        for (int j = 0; j < 4; j++)
#pragma unroll
            for (int q = 0; q < 4; q++) acc[i][j][q] = 0.f;

    gemm_issue_stage<SPLITS>(sb, tid, 0, s6, m0, n0);

    for (int c = 0; c < 32; c++) {
        if (c + 1 < 32) {
            gemm_issue_stage<SPLITS>(sb + ((c + 1) & 1) * STG, tid, (c + 1) * 64,
                                     s6, m0, n0);
            cp_wait<1>();
        } else {
            cp_wait<0>();
        }
        __syncthreads();
        const uint32_t st = sb + (c & 1) * STG;
#pragma unroll
        for (int ks = 0; ks < 4; ks++) {
            uint32_t af[SPLITS][4][4], bf[SPLITS][2][4];
#pragma unroll
            for (int mt = 0; mt < 4; mt++) {
                int arow = wm * 64 + mt * 16 + (lane & 15);
                int akc = ks * 2 + (lane >> 4);
                uint32_t off = (uint32_t)(arow << 7)
                             + (((uint32_t)(akc << 4)) ^ ((uint32_t)((arow & 7) << 4)));
#pragma unroll
                for (int s = 0; s < SPLITS; s++)
                    ldsm4(af[s][mt], st + s * 16384 + off);
            }
#pragma unroll
            for (int np = 0; np < 2; np++) {
                int mtx = lane >> 3;
                int brow = wn * 32 + np * 16 + (mtx >> 1) * 8 + (lane & 7);
                int bkc = ks * 2 + (mtx & 1);
                uint32_t off = (uint32_t)(brow << 7)
                             + (((uint32_t)(bkc << 4)) ^ ((uint32_t)((brow & 7) << 4)));
#pragma unroll
                for (int s = 0; s < SPLITS; s++)
                    ldsm4(bf[s][np], st + (SPLITS + s) * 16384 + off);
            }
#pragma unroll
            for (int mt = 0; mt < 4; mt++)
#pragma unroll
                for (int nt = 0; nt < 4; nt++) {
#pragma unroll
                    for (int i = 0; i < SPLITS; i++)
#pragma unroll
                        for (int j = 0; j < SPLITS; j++)
                            if (i + j < SPLITS)
                                mma_bf16(acc[mt][nt], af[i][mt],
                                         &bf[j][nt >> 1][(nt & 1) * 2]);
                }
        }
        __syncthreads();
    }
#pragma unroll
    for (int mt = 0; mt < 4; mt++) {
        int mrow = m0 + wm * 64 + mt * 16 + (lane >> 2);
#pragma unroll
        for (int nt = 0; nt < 4; nt++) {
            int n = n0 + wn * 32 + nt * 8 + (lane & 3) * 2;
            *(float2*)(C + (size_t)mrow * TD + n) =
                make_float2(acc[mt][nt][0], acc[mt][nt][1]);
            *(float2*)(C + (size_t)(mrow + 8) * TD + n) =
                make_float2(acc[mt][nt][2], acc[mt][nt][3]);
        }
    }
}

// ========== exact top-OMEGA select: radix + scan, sorted emission ========
struct SelSmem {
    float sv[CAP];
    int   sc[CAP];
    int   hist[256];
    int   wsum[8];
    int   woff[8];
    int   wsfx[8];
    unsigned prefix;
    int   rem;
    int   scnt;
};

__device__ __forceinline__ void select_sorted(const float acc[8], SelSmem& S)
{
    const int tid = threadIdx.x;
    const int lane = tid & 31, w = tid >> 5;
    unsigned key[8];
#pragma unroll
    for (int j = 0; j < 8; j++) key[j] = __float_as_uint(fabsf(acc[j]));
    if (tid == 0) { S.prefix = 0u; S.rem = KOM; }
    __syncthreads();
#pragma unroll
    for (int shift = 24; shift >= 0; shift -= 8) {
        S.hist[tid] = 0;
        __syncthreads();
        unsigned pref = S.prefix;
        int rem = S.rem;
        unsigned maskhi = (shift == 24) ? 0u : (0xFFFFFFFFu << (shift + 8));
#pragma unroll
        for (int j = 0; j < 8; j++)
            if ((key[j] & maskhi) == pref)
                atomicAdd(&S.hist[(key[j] >> shift) & 255], 1);
        __syncthreads();
        int h = S.hist[tid];
        int s = h;
#pragma unroll
        for (int d = 1; d < 32; d <<= 1) {
            int t = __shfl_down_sync(0xFFFFFFFFu, s, d);
            if (lane + d < 32) s += t;
        }
        if (lane == 0) S.wsfx[w] = s;
        __syncthreads();
        int above = 0;
        for (int ww = w + 1; ww < 8; ww++) above += S.wsfx[ww];
        int stot = s + above;
        bool hit = (stot >= rem) && (stot - h < rem);
        __syncthreads();
        if (hit) {
            S.prefix = pref | ((unsigned)tid << shift);
            S.rem = rem - (stot - h);
        }
        __syncthreads();
    }
    unsigned kth = S.prefix;
    int c = 0;
    bool keep[8];
#pragma unroll
    for (int j = 0; j < 8; j++) { keep[j] = key[j] >= kth; c += keep[j] ? 1 : 0; }
    int inc = c;
#pragma unroll
    for (int d = 1; d < 32; d <<= 1) {
        int t = __shfl_up_sync(0xFFFFFFFFu, inc, d);
        if (lane >= d) inc += t;
    }
    if (lane == 31) S.wsum[w] = inc;
    __syncthreads();
    if (tid == 0) {
        int run = 0;
#pragma unroll
        for (int ww = 0; ww < 8; ww++) { S.woff[ww] = run; run += S.wsum[ww]; }
        S.scnt = (run < CAP) ? run : CAP;
    }
    __syncthreads();
    int pos = S.woff[w] + inc - c;
#pragma unroll
    for (int j = 0; j < 8; j++) {
        if (keep[j] && pos < CAP) {
            S.sv[pos] = acc[j];
            S.sc[pos] = tid * 8 + j;
            pos++;
        }
    }
    __syncthreads();
}

__device__ __forceinline__ void gather_rows(
    const float* __restrict__ Mat, const SelSmem& S, int c0, float acc[8])
{
#pragma unroll
    for (int j = 0; j < 8; j++) acc[j] = 0.f;
    int cnt = S.scnt;
    for (int k = 0; k < cnt; k++) {
        float v = S.sv[k];
        const float* row = Mat + (size_t)S.sc[k] * TD + c0;
        float4 r0 = *(const float4*)row;
        float4 r1 = *(const float4*)(row + 4);
        acc[0] = fmaf(v, r0.x, acc[0]); acc[1] = fmaf(v, r0.y, acc[1]);
        acc[2] = fmaf(v, r0.z, acc[2]); acc[3] = fmaf(v, r0.w, acc[3]);
        acc[4] = fmaf(v, r1.x, acc[4]); acc[5] = fmaf(v, r1.y, acc[5]);
        acc[6] = fmaf(v, r1.z, acc[6]); acc[7] = fmaf(v, r1.w, acc[7]);
    }
}

// ---- z1 = thr(B); z2 = thr(B + S z1); emit z2 list to global ----------
__global__ __launch_bounds__(256) void z1z2_kernel(const float* __restrict__ Smat)
{
    __shared__ SelSmem SS;
    int b = blockIdx.x, tid = threadIdx.x;
    const int c0 = tid * 8;
    float b8[8];
    const float* bp = g_B + (size_t)b * TD + c0;
    *(float4*)&b8[0] = *(const float4*)bp;
    *(float4*)&b8[4] = *(const float4*)(bp + 4);
    select_sorted(b8, SS);                       // z1
    float acc[8];
    gather_rows(Smat, SS, c0, acc);              // S z1 (ascending cols, from 0)
#pragma unroll
    for (int j = 0; j < 8; j++) acc[j] += b8[j]; // + B last (matches ref order)
    __syncthreads();
    select_sorted(acc, SS);                      // z2
    for (int i = tid; i < SS.scnt; i += 256) {
        g_vals[b * CAP + i] = SS.sv[i];
        g_cols[b * CAP + i] = SS.sc[i];
    }
    if (tid == 0) g_cnt[b] = SS.scnt;
}

// ---- thr on dense T (after z_att GEMM), emit list to global -----------
__global__ __launch_bounds__(256) void thr_kernel(const float* __restrict__ T)
{
    __shared__ SelSmem SS;
    int b = blockIdx.x, tid = threadIdx.x;
    float acc[8];
    const float* tp = T + (size_t)b * TD + tid * 8;
    *(float4*)&acc[0] = *(const float4*)tp;
    *(float4*)&acc[4] = *(const float4*)(tp + 4);
    select_sorted(acc, SS);
    for (int i = tid; i < SS.scnt; i += 256) {
        g_vals[b * CAP + i] = SS.sv[i];
        g_cols[b * CAP + i] = SS.sc[i];
    }
    if (tid == 0) g_cnt[b] = SS.scnt;
}

// ---- v[b,:] = sum_k val_k * M[col_k,:]  (smooth use; order free) ------
__global__ __launch_bounds__(256) void vapply_kernel(const float* __restrict__ Mat)
{
    __shared__ float sv[CAP]; __shared__ int sc[CAP];
    int b = blockIdx.x, tid = threadIdx.x;
    int cnt = g_cnt[b];
    if (tid < CAP) { sv[tid] = g_vals[b * CAP + tid]; sc[tid] = g_cols[b * CAP + tid]; }
    __syncthreads();
    const int c0 = tid * 8;
    float acc[8];
#pragma unroll
    for (int j = 0; j < 8; j++) acc[j] = 0.f;
    for (int k = 0; k < cnt; k++) {
        float v = sv[k];
        const float* row = Mat + (size_t)sc[k] * TD + c0;
        float4 r0 = *(const float4*)row;
        float4 r1 = *(const float4*)(row + 4);
        acc[0] = fmaf(v, r0.x, acc[0]); acc[1] = fmaf(v, r0.y, acc[1]);
        acc[2] = fmaf(v, r0.z, acc[2]); acc[3] = fmaf(v, r0.w, acc[3]);
        acc[4] = fmaf(v, r1.x, acc[4]); acc[5] = fmaf(v, r1.y, acc[5]);
        acc[6] = fmaf(v, r1.z, acc[6]); acc[7] = fmaf(v, r1.w, acc[7]);
    }
    float* dp = g_V + (size_t)b * TD + c0;
    *(float4*)dp = *(float4*)&acc[0];
    *(float4*)(dp + 4) = *(float4*)&acc[4];
}

// ---- fused LIHT: 9 iterations + dense output + spectrum ---------------
__global__ __launch_bounds__(256) void liht_kernel(
    const float* __restrict__ Smat, float* __restrict__ out_z)
{
    __shared__ SelSmem SS;
    int b = blockIdx.x, tid = threadIdx.x;
    const int c0 = tid * 8;
    float b8[8];
    const float* bp = g_B + (size_t)b * TD + c0;
    *(float4*)&b8[0] = *(const float4*)bp;
    *(float4*)&b8[4] = *(const float4*)(bp + 4);
    int cnt = g_cnt[b];
    if (tid < CAP) {
        SS.sv[tid] = g_vals[b * CAP + tid];
        SS.sc[tid] = g_cols[b * CAP + tid];
    }
    if (tid == 0) SS.scnt = cnt;
    __syncthreads();

    float acc[8];
    for (int it = 0; it < 9; it++) {
        gather_rows(Smat, SS, c0, acc);
#pragma unroll
        for (int j = 0; j < 8; j++) acc[j] += b8[j];
        __syncthreads();
        select_sorted(acc, SS);
    }
    unsigned kth = SS.prefix;
    float o[8];
#pragma unroll
    for (int j = 0; j < 8; j++) {
        bool keep = __float_as_uint(fabsf(acc[j])) >= kth;
        o[j] = keep ? acc[j] : 0.f;
        if (keep) atomicAdd(&g_mD[(c0 + j) & 1023], acc[j] * acc[j]);
    }
    float* dp = out_z + (size_t)b * TD + c0;
    *(float4*)dp = *(float4*)&o[0];
    *(float4*)(dp + 4) = *(float4*)&o[4];
}

// ------- attention: raw scores, softmax over batch axis, weighted sum ----
__global__ __launch_bounds__(256) void att_dot_kernel(const float* __restrict__ prev)
{
    int b = blockIdx.x, p = blockIdx.y, tid = threadIdx.x;
    const float* pr = prev + ((size_t)p * NB + b) * TD + tid * 8;
    const float* v = g_V + (size_t)b * TD + tid * 8;
    float4 a0 = *(const float4*)pr, a1 = *(const float4*)(pr + 4);
    float4 b0 = *(const float4*)v, b1 = *(const float4*)(v + 4);
    float s = a0.x * b0.x + a0.y * b0.y + a0.z * b0.z + a0.w * b0.w
            + a1.x * b1.x + a1.y * b1.y + a1.z * b1.z + a1.w * b1.w;
    __shared__ float red[256];
    red[tid] = s; __syncthreads();
    for (int off = 128; off > 0; off >>= 1) {
        if (tid < off) red[tid] += red[tid + off];
        __syncthreads();
    }
    if (tid == 0) g_attraw[p * NB + b] = red[0];
}

__global__ __launch_bounds__(256) void softmax_kernel()
{
    int p = blockIdx.x, tid = threadIdx.x;
    float x[8];
#pragma unroll
    for (int j = 0; j < 8; j++) x[j] = g_attraw[p * NB + tid + j * 256];
    __shared__ float red[256];
    float m = x[0];
#pragma unroll
    for (int j = 1; j < 8; j++) m = fmaxf(m, x[j]);
    red[tid] = m; __syncthreads();
    for (int off = 128; off > 0; off >>= 1) {
        if (tid < off) red[tid] = fmaxf(red[tid], red[tid + off]);
        __syncthreads();
    }
    m = red[0]; __syncthreads();
    float s = 0.f;
#pragma unroll
    for (int j = 0; j < 8; j++) { x[j] = expf(x[j] - m); s += x[j]; }
    red[tid] = s; __syncthreads();
    for (int off = 128; off > 0; off >>= 1) {
        if (tid < off) red[tid] += red[tid + off];
        __syncthreads();
    }
    float inv = 1.f / red[0];
#pragma unroll
    for (int j = 0; j < 8; j++) g_att[p * NB + tid + j * 256] = x[j] * inv;
}

__global__ __launch_bounds__(256) void zatt_kernel(
    const float* __restrict__ prev, const float* __restrict__ lambda2)
{
    int b = blockIdx.x, tid = threadIdx.x;
    __shared__ float a[NP];
    if (tid < NP) a[tid] = g_att[tid * NB + b];
    __syncthreads();
    float l2 = *lambda2;
#pragma unroll
    for (int j = 0; j < 8; j++) {
        int d = tid + j * 256;
        float s = 0.f;
#pragma unroll
        for (int p = 0; p < NP; p++) {
            float w = prev[((size_t)p * NB + b) * TD + d];
            w = fminf(fmaxf(w, -150.f), 150.f);
            s = fmaf(w, a[p], s);
        }
        g_V[(size_t)b * TD + d] = l2 * s;    // v consumed; reuse as z_att
    }
}

// ------- spectrum normalize -----------------------------------------
__global__ void zero_mD_kernel() { g_mD[threadIdx.x] = 0.f; }

__global__ __launch_bounds__(256) void norm_kernel(float* __restrict__ out)
{
    int tid = threadIdx.x;
    float x[4];
#pragma unroll
    for (int j = 0; j < 4; j++) x[j] = g_mD[tid + j * 256];
    __shared__ float rmn[256], rmx[256];
    float mn = x[0], mx = x[0];
#pragma unroll
    for (int j = 1; j < 4; j++) { mn = fminf(mn, x[j]); mx = fmaxf(mx, x[j]); }
    rmn[tid] = mn; rmx[tid] = mx; __syncthreads();
    for (int off = 128; off > 0; off >>= 1) {
        if (tid < off) {
            rmn[tid] = fminf(rmn[tid], rmn[tid + off]);
            rmx[tid] = fmaxf(rmx[tid], rmx[tid + off]);
        }
        __syncthreads();
    }
    mn = rmn[0]; mx = rmx[0];
    float inv = 1.f / (mx - mn + 1e-8f);
#pragma unroll
    for (int j = 0; j < 4; j++) out[tid + j * 256] = (x[j] - mn) * inv;
}

// ------------------------------- driver ---------------------------------
extern "C" void kernel_launch(void* const* d_in, const int* in_sizes, int n_in,
                              void* d_out, int out_size)
{
    const float* x       = (const float*)d_in[0];  // (2048, 2048)
    const float* prev    = (const float*)d_in[1];  // (8, 2048, 2048)
    const float* Wd      = (const float*)d_in[2];  // (2048, 2048)
    const float* S       = (const float*)d_in[3];  // (2048, 2048), symmetric
    const float* lambda2 = (const float*)d_in[4];  // scalar

    float* out    = (float*)d_out;
    float* out_mD = out;           // (1024,)
    float* out_z  = out + 1024;    // (2048, 2048)

    float *pB, *pM, *pT, *pV;
    __nv_bfloat16 *wh, *wm, *wl, *wth, *wtm, *wtl;
    cudaGetSymbolAddress((void**)&pB, g_B);
    cudaGetSymbolAddress((void**)&pM, g_M);
    cudaGetSymbolAddress((void**)&pT, g_T);
    cudaGetSymbolAddress((void**)&pV, g_V);
    cudaGetSymbolAddress((void**)&wh, g_wh);   cudaGetSymbolAddress((void**)&wm, g_wm);
    cudaGetSymbolAddress((void**)&wl, g_wl);
    cudaGetSymbolAddress((void**)&wth, g_wth); cudaGetSymbolAddress((void**)&wtm, g_wtm);
    cudaGetSymbolAddress((void**)&wtl, g_wtl);

    const int SMEM3 = 3 * 2 * 16384 * 2;   // 196608
    cudaFuncSetAttribute(mma_gemm_kernel<3>,
                         cudaFuncAttributeMaxDynamicSharedMemorySize, SMEM3);

    const int SPLIT_BLKS = (int)(((size_t)TD * TD) / 1024);
    dim3 g16(16, 16);

    zero_mD_kernel<<<1, 1024>>>();
    // B = x @ Wd^T  (fp32 ascending-k chain: selection-critical)
    sgemm2_kernel<1, 0><<<g16, 128>>>(x, Wd, nullptr, pB);
    // z1, z2 fused (sorted sparse sums; +B last to match ref rounding)
    z1z2_kernel<<<NB, 256>>>(S);
    // M = Wd @ Wd  (tensor 3-split; feeds softmax only)
    split3_kernel<<<SPLIT_BLKS, 256>>>(Wd, wh, wm, wl);
    tsplit3_kernel<<<dim3(64, 64), dim3(32, 8)>>>(Wd, wth, wtm, wtl);
    mma_gemm_kernel<3><<<g16, 256, SMEM3>>>(wh, wm, wl, wth, wtm, wtl, pM);
    // v = sparse(z2) . M rows
    vapply_kernel<<<NB, 256>>>(pM);
    // attention + z_att
    att_dot_kernel<<<dim3(NB, NP), 256>>>(prev);
    softmax_kernel<<<NP, 256>>>();
    zatt_kernel<<<NB, 256>>>(prev, lambda2);
    // LIHT iter 1 (dense): T = z_att @ S + B  (fp32 chain, +B last)
    sgemm2_kernel<0, 1><<<g16, 128>>>(pV, S, pB, pT);
    thr_kernel<<<NB, 256>>>(pT);
    // LIHT iters 2..10 fused + spectrum + dense out
    liht_kernel<<<NB, 256>>>(S, out_z);
    norm_kernel<<<1, 256>>>(out_mD);

    (void)in_sizes; (void)n_in; (void)out_size;
}

// round 16
// speedup vs baseline: 2.3829x; 1.0628x over previous
#include <cuda_runtime.h>
#include <cuda_bf16.h>
#include <cstdint>
#include <cstring>

#define TD 2048      // D = 2*W
#define NB 2048      // BATCH
#define NP 8         // P previous windows
#define KOM 50       // OMEGA
#define CAP 64       // sparse capacity per row

// ------------------- scratch (static device globals) -------------------
__device__ float g_B[(size_t)NB * TD];
__device__ float g_M[(size_t)TD * TD];
__device__ float g_T[(size_t)NB * TD];
__device__ float g_V[(size_t)NB * TD];
__device__ __nv_bfloat16 g_wh[(size_t)TD * TD], g_wm[(size_t)TD * TD], g_wl[(size_t)TD * TD];
__device__ __nv_bfloat16 g_wth[(size_t)TD * TD], g_wtm[(size_t)TD * TD], g_wtl[(size_t)TD * TD];
__device__ float g_vals[NB * CAP];
__device__ int   g_cols[NB * CAP];
__device__ int   g_cnt[NB];
__device__ float g_attraw[NP * NB];
__device__ float g_att[NP * NB];
__device__ float g_mD[1024];

// ---------------- packed f32x2 helpers (SASS FFMA2) ---------------------
// Each half is an independent IEEE rn fp32 FMA -> bitwise == scalar fmaf.
typedef unsigned long long u64;
__device__ __forceinline__ void fma2(u64& d, u64 a, u64 b) {
    asm("fma.rn.f32x2 %0, %1, %2, %0;" : "+l"(d) : "l"(a), "l"(b));
}
__device__ __forceinline__ u64 splat2(unsigned int x) {
    u64 r; asm("mov.b64 %0, {%1, %1};" : "=l"(r) : "r"(x)); return r;
}
__device__ __forceinline__ float pel(u64 v, int h) {
    uint2 u; memcpy(&u, &v, 8);
    return __uint_as_float(h ? u.y : u.x);
}

// ========== fp32 GEMM v3: FFMA2 (f32x2), 16x8 rtile, 128 thr, BK=8 ======
// C[m,n] = (ADD_BASE? Base[m,n]:0) + sum_k A[m,k]*(TRANS_B ? Bm[n,k] : Bm[k,n])
// acc paired along m; each element keeps its ascending-k rn-fma chain
// (bitwise identical to sgemm2 / R4 sgemm).
template<int TRANS_B, int ADD_BASE>
__global__ __launch_bounds__(128, 2) void sgemm3_kernel(
    const float* __restrict__ A, const float* __restrict__ Bm,
    const float* __restrict__ Base, float* __restrict__ C)
{
    __shared__ float As[2][8][132];
    __shared__ float Bs[2][8][132];
    const int tid = threadIdx.x;
    const int tx = tid & 15, ty = tid >> 4;          // tx: n-group, ty: m-group
    const int m0 = blockIdx.y * 128, n0 = blockIdx.x * 128;

    const int idx0 = tid, idx1 = tid + 128;
    const int am0 = idx0 >> 1, akc0 = (idx0 & 1) * 4;
    const int am1 = idx1 >> 1, akc1 = (idx1 & 1) * 4;
    const int bk0 = idx0 >> 5, bnc0 = (idx0 & 31) * 4;   // non-trans B
    const int bk1 = idx1 >> 5, bnc1 = (idx1 & 31) * 4;

    u64 accp[8][8];                                   // [m-pair][n]
#pragma unroll
    for (int i = 0; i < 8; i++)
#pragma unroll
        for (int j = 0; j < 8; j++) accp[i][j] = 0ull;

    float4 ar0, ar1, br0, br1;
    ar0 = *(const float4*)(A + (size_t)(m0 + am0) * TD + akc0);
    ar1 = *(const float4*)(A + (size_t)(m0 + am1) * TD + akc1);
    if (TRANS_B) {
        br0 = *(const float4*)(Bm + (size_t)(n0 + am0) * TD + akc0);
        br1 = *(const float4*)(Bm + (size_t)(n0 + am1) * TD + akc1);
    } else {
        br0 = *(const float4*)(Bm + (size_t)bk0 * TD + n0 + bnc0);
        br1 = *(const float4*)(Bm + (size_t)bk1 * TD + n0 + bnc1);
    }
    {
        As[0][akc0 + 0][am0] = ar0.x; As[0][akc0 + 1][am0] = ar0.y;
        As[0][akc0 + 2][am0] = ar0.z; As[0][akc0 + 3][am0] = ar0.w;
        As[0][akc1 + 0][am1] = ar1.x; As[0][akc1 + 1][am1] = ar1.y;
        As[0][akc1 + 2][am1] = ar1.z; As[0][akc1 + 3][am1] = ar1.w;
        if (TRANS_B) {
            Bs[0][akc0 + 0][am0] = br0.x; Bs[0][akc0 + 1][am0] = br0.y;
            Bs[0][akc0 + 2][am0] = br0.z; Bs[0][akc0 + 3][am0] = br0.w;
            Bs[0][akc1 + 0][am1] = br1.x; Bs[0][akc1 + 1][am1] = br1.y;
            Bs[0][akc1 + 2][am1] = br1.z; Bs[0][akc1 + 3][am1] = br1.w;
        } else {
            *(float4*)&Bs[0][bk0][bnc0] = br0;
            *(float4*)&Bs[0][bk1][bnc1] = br1;
        }
    }
    __syncthreads();

    for (int kb = 0; kb < 256; kb++) {
        const int cur = kb & 1;
        if (kb < 255) {
            const int k0n = (kb + 1) * 8;
            ar0 = *(const float4*)(A + (size_t)(m0 + am0) * TD + k0n + akc0);
            ar1 = *(const float4*)(A + (size_t)(m0 + am1) * TD + k0n + akc1);
            if (TRANS_B) {
                br0 = *(const float4*)(Bm + (size_t)(n0 + am0) * TD + k0n + akc0);
                br1 = *(const float4*)(Bm + (size_t)(n0 + am1) * TD + k0n + akc1);
            } else {
                br0 = *(const float4*)(Bm + (size_t)(k0n + bk0) * TD + n0 + bnc0);
                br1 = *(const float4*)(Bm + (size_t)(k0n + bk1) * TD + n0 + bnc1);
            }
        }
#pragma unroll
        for (int kk = 0; kk < 8; kk++) {
            // a pairs (adjacent m) come packed straight from smem
            ulonglong2 a01 = *(const ulonglong2*)&As[cur][kk][ty * 16 + 0];
            ulonglong2 a23 = *(const ulonglong2*)&As[cur][kk][ty * 16 + 4];
            ulonglong2 a45 = *(const ulonglong2*)&As[cur][kk][ty * 16 + 8];
            ulonglong2 a67 = *(const ulonglong2*)&As[cur][kk][ty * 16 + 12];
            u64 ap[8] = {a01.x, a01.y, a23.x, a23.y, a45.x, a45.y, a67.x, a67.y};
            uint4 b0 = *(const uint4*)&Bs[cur][kk][tx * 8 + 0];
            uint4 b1 = *(const uint4*)&Bs[cur][kk][tx * 8 + 4];
            u64 bs[8] = {splat2(b0.x), splat2(b0.y), splat2(b0.z), splat2(b0.w),
                         splat2(b1.x), splat2(b1.y), splat2(b1.z), splat2(b1.w)};
#pragma unroll
            for (int ip = 0; ip < 8; ip++)
#pragma unroll
                for (int j = 0; j < 8; j++) fma2(accp[ip][j], ap[ip], bs[j]);
        }
        if (kb < 255) {
            const int nb = cur ^ 1;
            As[nb][akc0 + 0][am0] = ar0.x; As[nb][akc0 + 1][am0] = ar0.y;
            As[nb][akc0 + 2][am0] = ar0.z; As[nb][akc0 + 3][am0] = ar0.w;
            As[nb][akc1 + 0][am1] = ar1.x; As[nb][akc1 + 1][am1] = ar1.y;
            As[nb][akc1 + 2][am1] = ar1.z; As[nb][akc1 + 3][am1] = ar1.w;
            if (TRANS_B) {
                Bs[nb][akc0 + 0][am0] = br0.x; Bs[nb][akc0 + 1][am0] = br0.y;
                Bs[nb][akc0 + 2][am0] = br0.z; Bs[nb][akc0 + 3][am0] = br0.w;
                Bs[nb][akc1 + 0][am1] = br1.x; Bs[nb][akc1 + 1][am1] = br1.y;
                Bs[nb][akc1 + 2][am1] = br1.z; Bs[nb][akc1 + 3][am1] = br1.w;
            } else {
                *(float4*)&Bs[nb][bk0][bnc0] = br0;
                *(float4*)&Bs[nb][bk1][bnc1] = br1;
            }
            __syncthreads();
        }
    }

#pragma unroll
    for (int ip = 0; ip < 8; ip++) {
#pragma unroll
        for (int h = 0; h < 2; h++) {
            int m = m0 + ty * 16 + ip * 2 + h;
#pragma unroll
            for (int j = 0; j < 8; j += 4) {
                int n = n0 + tx * 8 + j;
                float4 o;
                o.x = pel(accp[ip][j + 0], h); o.y = pel(accp[ip][j + 1], h);
                o.z = pel(accp[ip][j + 2], h); o.w = pel(accp[ip][j + 3], h);
                if (ADD_BASE) {
                    float4 bb = *(const float4*)(Base + (size_t)m * TD + n);
                    o.x += bb.x; o.y += bb.y; o.z += bb.z; o.w += bb.w;
                }
                *(float4*)(C + (size_t)m * TD + n) = o;
            }
        }
    }
}

// ========== tensor-core 3-split GEMM (for M only; smooth use) ===========
__device__ __forceinline__ uint32_t smem_u32(const void* p) {
    uint32_t a;
    asm("{ .reg .u64 t; cvta.to.shared.u64 t, %1; cvt.u32.u64 %0, t; }"
        : "=r"(a) : "l"(p));
    return a;
}
__device__ __forceinline__ void cp_async16(uint32_t dst, const void* src) {
    asm volatile("cp.async.cg.shared.global [%0], [%1], 16;" :: "r"(dst), "l"(src));
}
__device__ __forceinline__ void cp_commit() {
    asm volatile("cp.async.commit_group;" ::: "memory");
}
template<int N> __device__ __forceinline__ void cp_wait() {
    asm volatile("cp.async.wait_group %0;" :: "n"(N) : "memory");
}
__device__ __forceinline__ void ldsm4(uint32_t* r, uint32_t a) {
    asm volatile("ldmatrix.sync.aligned.m8n8.x4.shared.b16 {%0,%1,%2,%3}, [%4];"
        : "=r"(r[0]), "=r"(r[1]), "=r"(r[2]), "=r"(r[3]) : "r"(a));
}
__device__ __forceinline__ void mma_bf16(float* c, const uint32_t* a, const uint32_t* b) {
    asm volatile(
        "mma.sync.aligned.m16n8k16.row.col.f32.bf16.bf16.f32 "
        "{%0,%1,%2,%3}, {%4,%5,%6,%7}, {%8,%9}, {%0,%1,%2,%3};"
        : "+f"(c[0]), "+f"(c[1]), "+f"(c[2]), "+f"(c[3])
        : "r"(a[0]), "r"(a[1]), "r"(a[2]), "r"(a[3]), "r"(b[0]), "r"(b[1]));
}

__global__ __launch_bounds__(256) void split3_kernel(
    const float* __restrict__ X, __nv_bfloat16* __restrict__ H,
    __nv_bfloat16* __restrict__ M, __nv_bfloat16* __restrict__ Lo)
{
    size_t i = ((size_t)blockIdx.x * 256 + threadIdx.x) * 4;
    float4 v = *(const float4*)(X + i);
    float f[4] = {v.x, v.y, v.z, v.w};
    __nv_bfloat16 hh[4], mm[4], ll[4];
#pragma unroll
    for (int j = 0; j < 4; j++) {
        hh[j] = __float2bfloat16(f[j]);
        float r = f[j] - __bfloat162float(hh[j]);
        mm[j] = __float2bfloat16(r);
        ll[j] = __float2bfloat16(r - __bfloat162float(mm[j]));
    }
    *(uint2*)(H + i) = *(uint2*)hh;
    *(uint2*)(M + i) = *(uint2*)mm;
    *(uint2*)(Lo + i) = *(uint2*)ll;
}

__global__ void tsplit3_kernel(const float* __restrict__ X,
                               __nv_bfloat16* __restrict__ H,
                               __nv_bfloat16* __restrict__ M,
                               __nv_bfloat16* __restrict__ Lo)
{
    __shared__ float t[32][33];
    int bx = blockIdx.x * 32, by = blockIdx.y * 32;
    int tx = threadIdx.x, ty = threadIdx.y;   // (32, 8)
#pragma unroll
    for (int r = 0; r < 32; r += 8)
        t[ty + r][tx] = X[(size_t)(by + ty + r) * TD + bx + tx];
    __syncthreads();
#pragma unroll
    for (int r = 0; r < 32; r += 8) {
        float v = t[tx][ty + r];
        size_t o = (size_t)(bx + ty + r) * TD + by + tx;
        __nv_bfloat16 h = __float2bfloat16(v);
        float rr = v - __bfloat162float(h);
        __nv_bfloat16 m = __float2bfloat16(rr);
        H[o] = h; M[o] = m;
        Lo[o] = __float2bfloat16(rr - __bfloat162float(m));
    }
}

template<int SPLITS>
__device__ __forceinline__ void gemm_issue_stage(
    uint32_t dbase, int tid, int k0,
    const __nv_bfloat16* const* srcs, int m0, int n0)
{
#pragma unroll
    for (int op = 0; op < 2 * SPLITS; op++) {
        const __nv_bfloat16* src = srcs[op];
        const int r0 = (op < SPLITS) ? m0 : n0;
#pragma unroll
        for (int i = 0; i < 4; i++) {
            int idx = tid + i * 256;
            int row = idx >> 3, ch = idx & 7;
            uint32_t dst = dbase + op * 16384 + (uint32_t)(row << 7)
                         + (((uint32_t)(ch << 4)) ^ ((uint32_t)((row & 7) << 4)));
            cp_async16(dst, src + (size_t)(r0 + row) * TD + k0 + ch * 8);
        }
    }
    cp_commit();
}

template<int SPLITS>
__global__ __launch_bounds__(256, 1) void mma_gemm_kernel(
    const __nv_bfloat16* __restrict__ A0, const __nv_bfloat16* __restrict__ A1,
    const __nv_bfloat16* __restrict__ A2,
    const __nv_bfloat16* __restrict__ B0, const __nv_bfloat16* __restrict__ B1,
    const __nv_bfloat16* __restrict__ B2,
    float* __restrict__ C)
{
    extern __shared__ char smem[];
    const uint32_t sb = smem_u32(smem);
    const uint32_t STG = SPLITS * 2 * 16384;
    const int tid = threadIdx.x;
    const int wid = tid >> 5, lane = tid & 31;
    const int wm = wid >> 2, wn = wid & 3;
    const int m0 = blockIdx.y * 128, n0 = blockIdx.x * 128;

    const __nv_bfloat16* srcs[6] = {A0, A1, A2, B0, B1, B2};
    const __nv_bfloat16* s6[2 * SPLITS];
#pragma unroll
    for (int i = 0; i < SPLITS; i++) { s6[i] = srcs[i]; s6[SPLITS + i] = srcs[3 + i]; }

    float acc[4][4][4];
#pragma unroll
    for (int i = 0; i < 4; i++)
#pragma unroll
        for (int j = 0; j < 4; j++)
#pragma unroll
            for (int q = 0; q < 4; q++) acc[i][j][q] = 0.f;

    gemm_issue_stage<SPLITS>(sb, tid, 0, s6, m0, n0);

    for (int c = 0; c < 32; c++) {
        if (c + 1 < 32) {
            gemm_issue_stage<SPLITS>(sb + ((c + 1) & 1) * STG, tid, (c + 1) * 64,
                                     s6, m0, n0);
            cp_wait<1>();
        } else {
            cp_wait<0>();
        }
        __syncthreads();
        const uint32_t st = sb + (c & 1) * STG;
#pragma unroll
        for (int ks = 0; ks < 4; ks++) {
            uint32_t af[SPLITS][4][4], bf[SPLITS][2][4];
#pragma unroll
            for (int mt = 0; mt < 4; mt++) {
                int arow = wm * 64 + mt * 16 + (lane & 15);
                int akc = ks * 2 + (lane >> 4);
                uint32_t off = (uint32_t)(arow << 7)
                             + (((uint32_t)(akc << 4)) ^ ((uint32_t)((arow & 7) << 4)));
#pragma unroll
                for (int s = 0; s < SPLITS; s++)
                    ldsm4(af[s][mt], st + s * 16384 + off);
            }
#pragma unroll
            for (int np = 0; np < 2; np++) {
                int mtx = lane >> 3;
                int brow = wn * 32 + np * 16 + (mtx >> 1) * 8 + (lane & 7);
                int bkc = ks * 2 + (mtx & 1);
                uint32_t off = (uint32_t)(brow << 7)
                             + (((uint32_t)(bkc << 4)) ^ ((uint32_t)((brow & 7) << 4)));
#pragma unroll
                for (int s = 0; s < SPLITS; s++)
                    ldsm4(bf[s][np], st + (SPLITS + s) * 16384 + off);
            }
#pragma unroll
            for (int mt = 0; mt < 4; mt++)
#pragma unroll
                for (int nt = 0; nt < 4; nt++) {
#pragma unroll
                    for (int i = 0; i < SPLITS; i++)
#pragma unroll
                        for (int j = 0; j < SPLITS; j++)
                            if (i + j < SPLITS)
                                mma_bf16(acc[mt][nt], af[i][mt],
                                         &bf[j][nt >> 1][(nt & 1) * 2]);
                }
        }
        __syncthreads();
    }
#pragma unroll
    for (int mt = 0; mt < 4; mt++) {
        int mrow = m0 + wm * 64 + mt * 16 + (lane >> 2);
#pragma unroll
        for (int nt = 0; nt < 4; nt++) {
            int n = n0 + wn * 32 + nt * 8 + (lane & 3) * 2;
            *(float2*)(C + (size_t)mrow * TD + n) =
                make_float2(acc[mt][nt][0], acc[mt][nt][1]);
            *(float2*)(C + (size_t)(mrow + 8) * TD + n) =
                make_float2(acc[mt][nt][2], acc[mt][nt][3]);
        }
    }
}

// ========== exact top-OMEGA select: radix + scan, sorted emission ========
struct SelSmem {
    float sv[CAP];
    int   sc[CAP];
    int   hist[256];
    int   wsum[8];
    int   woff[8];
    int   wsfx[8];
    unsigned prefix;
    int   rem;
    int   scnt;
};

__device__ __forceinline__ void select_sorted(const float acc[8], SelSmem& S)
{
    const int tid = threadIdx.x;
    const int lane = tid & 31, w = tid >> 5;
    unsigned key[8];
#pragma unroll
    for (int j = 0; j < 8; j++) key[j] = __float_as_uint(fabsf(acc[j]));
    if (tid == 0) { S.prefix = 0u; S.rem = KOM; }
    __syncthreads();
#pragma unroll
    for (int shift = 24; shift >= 0; shift -= 8) {
        S.hist[tid] = 0;
        __syncthreads();
        unsigned pref = S.prefix;
        int rem = S.rem;
        unsigned maskhi = (shift == 24) ? 0u : (0xFFFFFFFFu << (shift + 8));
#pragma unroll
        for (int j = 0; j < 8; j++)
            if ((key[j] & maskhi) == pref)
                atomicAdd(&S.hist[(key[j] >> shift) & 255], 1);
        __syncthreads();
        int h = S.hist[tid];
        int s = h;
#pragma unroll
        for (int d = 1; d < 32; d <<= 1) {
            int t = __shfl_down_sync(0xFFFFFFFFu, s, d);
            if (lane + d < 32) s += t;
        }
        if (lane == 0) S.wsfx[w] = s;
        __syncthreads();
        int above = 0;
        for (int ww = w + 1; ww < 8; ww++) above += S.wsfx[ww];
        int stot = s + above;
        bool hit = (stot >= rem) && (stot - h < rem);
        __syncthreads();
        if (hit) {
            S.prefix = pref | ((unsigned)tid << shift);
            S.rem = rem - (stot - h);
        }
        __syncthreads();
    }
    unsigned kth = S.prefix;
    int c = 0;
    bool keep[8];
#pragma unroll
    for (int j = 0; j < 8; j++) { keep[j] = key[j] >= kth; c += keep[j] ? 1 : 0; }
    int inc = c;
#pragma unroll
    for (int d = 1; d < 32; d <<= 1) {
        int t = __shfl_up_sync(0xFFFFFFFFu, inc, d);
        if (lane >= d) inc += t;
    }
    if (lane == 31) S.wsum[w] = inc;
    __syncthreads();
    if (tid == 0) {
        int run = 0;
#pragma unroll
        for (int ww = 0; ww < 8; ww++) { S.woff[ww] = run; run += S.wsum[ww]; }
        S.scnt = (run < CAP) ? run : CAP;
    }
    __syncthreads();
    int pos = S.woff[w] + inc - c;
#pragma unroll
    for (int j = 0; j < 8; j++) {
        if (keep[j] && pos < CAP) {
            S.sv[pos] = acc[j];
            S.sc[pos] = tid * 8 + j;
            pos++;
        }
    }
    __syncthreads();
}

// gather acc = sum_k sv[k]*Mat[sc[k], c0..] with FFMA2 pairs; each element's
// rn-fma chain (ascending k, from 0) is bitwise == the scalar version.
__device__ __forceinline__ void gather_rows(
    const float* __restrict__ Mat, const SelSmem& S, int c0, float acc[8])
{
    u64 ap[4] = {0ull, 0ull, 0ull, 0ull};
    int cnt = S.scnt;
    for (int k = 0; k < cnt; k++) {
        u64 vs = splat2(__float_as_uint(S.sv[k]));
        const float* row = Mat + (size_t)S.sc[k] * TD + c0;
        ulonglong2 r0 = *(const ulonglong2*)row;
        ulonglong2 r1 = *(const ulonglong2*)(row + 4);
        fma2(ap[0], r0.x, vs); fma2(ap[1], r0.y, vs);
        fma2(ap[2], r1.x, vs); fma2(ap[3], r1.y, vs);
    }
#pragma unroll
    for (int q = 0; q < 4; q++) {
        acc[2 * q]     = pel(ap[q], 0);
        acc[2 * q + 1] = pel(ap[q], 1);
    }
}

// ---- z1 = thr(B); z2 = thr(B + S z1); emit z2 list to global ----------
__global__ __launch_bounds__(256) void z1z2_kernel(const float* __restrict__ Smat)
{
    __shared__ SelSmem SS;
    int b = blockIdx.x, tid = threadIdx.x;
    const int c0 = tid * 8;
    float b8[8];
    const float* bp = g_B + (size_t)b * TD + c0;
    *(float4*)&b8[0] = *(const float4*)bp;
    *(float4*)&b8[4] = *(const float4*)(bp + 4);
    select_sorted(b8, SS);                       // z1
    float acc[8];
    gather_rows(Smat, SS, c0, acc);              // S z1 (ascending cols, from 0)
#pragma unroll
    for (int j = 0; j < 8; j++) acc[j] += b8[j]; // + B last (matches ref order)
    __syncthreads();
    select_sorted(acc, SS);                      // z2
    for (int i = tid; i < SS.scnt; i += 256) {
        g_vals[b * CAP + i] = SS.sv[i];
        g_cols[b * CAP + i] = SS.sc[i];
    }
    if (tid == 0) g_cnt[b] = SS.scnt;
}

// ---- thr on dense T (after z_att GEMM), emit list to global -----------
__global__ __launch_bounds__(256) void thr_kernel(const float* __restrict__ T)
{
    __shared__ SelSmem SS;
    int b = blockIdx.x, tid = threadIdx.x;
    float acc[8];
    const float* tp = T + (size_t)b * TD + tid * 8;
    *(float4*)&acc[0] = *(const float4*)tp;
    *(float4*)&acc[4] = *(const float4*)(tp + 4);
    select_sorted(acc, SS);
    for (int i = tid; i < SS.scnt; i += 256) {
        g_vals[b * CAP + i] = SS.sv[i];
        g_cols[b * CAP + i] = SS.sc[i];
    }
    if (tid == 0) g_cnt[b] = SS.scnt;
}

// ---- fused v + attention dots: v stays in registers -------------------
// v[b,:] = sum_k val_k * M[col_k,:]; attraw[p,b] = prev[p,b,:] . v[b,:]
__global__ __launch_bounds__(256) void vatt_kernel(
    const float* __restrict__ Mat, const float* __restrict__ prev)
{
    __shared__ float sv[CAP]; __shared__ int sc[CAP];
    __shared__ float w8[NP][8];
    int b = blockIdx.x, tid = threadIdx.x;
    int lane = tid & 31, w = tid >> 5;
    int cnt = g_cnt[b];
    if (tid < CAP) { sv[tid] = g_vals[b * CAP + tid]; sc[tid] = g_cols[b * CAP + tid]; }
    __syncthreads();
    const int c0 = tid * 8;
    u64 ap[4] = {0ull, 0ull, 0ull, 0ull};
    for (int k = 0; k < cnt; k++) {
        u64 vs = splat2(__float_as_uint(sv[k]));
        const float* row = Mat + (size_t)sc[k] * TD + c0;
        ulonglong2 r0 = *(const ulonglong2*)row;
        ulonglong2 r1 = *(const ulonglong2*)(row + 4);
        fma2(ap[0], r0.x, vs); fma2(ap[1], r0.y, vs);
        fma2(ap[2], r1.x, vs); fma2(ap[3], r1.y, vs);
    }
    float v8[8];
#pragma unroll
    for (int q = 0; q < 4; q++) { v8[2 * q] = pel(ap[q], 0); v8[2 * q + 1] = pel(ap[q], 1); }
#pragma unroll
    for (int p = 0; p < NP; p++) {
        const float* pr = prev + ((size_t)p * NB + b) * TD + c0;
        float4 a0 = *(const float4*)pr, a1 = *(const float4*)(pr + 4);
        float s = a0.x * v8[0] + a0.y * v8[1] + a0.z * v8[2] + a0.w * v8[3]
                + a1.x * v8[4] + a1.y * v8[5] + a1.z * v8[6] + a1.w * v8[7];
#pragma unroll
        for (int d = 16; d > 0; d >>= 1) s += __shfl_down_sync(0xFFFFFFFFu, s, d);
        if (lane == 0) w8[p][w] = s;
    }
    __syncthreads();
    if (tid < NP) {
        float s = 0.f;
#pragma unroll
        for (int ww = 0; ww < 8; ww++) s += w8[tid][ww];
        g_attraw[tid * NB + b] = s;
    }
}

// ---- fused LIHT: 9 iterations + dense output + spectrum ---------------
__global__ __launch_bounds__(256) void liht_kernel(
    const float* __restrict__ Smat, float* __restrict__ out_z)
{
    __shared__ SelSmem SS;
    int b = blockIdx.x, tid = threadIdx.x;
    const int c0 = tid * 8;
    float b8[8];
    const float* bp = g_B + (size_t)b * TD + c0;
    *(float4*)&b8[0] = *(const float4*)bp;
    *(float4*)&b8[4] = *(const float4*)(bp + 4);
    int cnt = g_cnt[b];
    if (tid < CAP) {
        SS.sv[tid] = g_vals[b * CAP + tid];
        SS.sc[tid] = g_cols[b * CAP + tid];
    }
    if (tid == 0) SS.scnt = cnt;
    __syncthreads();

    float acc[8];
    for (int it = 0; it < 9; it++) {
        gather_rows(Smat, SS, c0, acc);
#pragma unroll
        for (int j = 0; j < 8; j++) acc[j] += b8[j];
        __syncthreads();
        select_sorted(acc, SS);
    }
    unsigned kth = SS.prefix;
    float o[8];
#pragma unroll
    for (int j = 0; j < 8; j++) {
        bool keep = __float_as_uint(fabsf(acc[j])) >= kth;
        o[j] = keep ? acc[j] : 0.f;
        if (keep) atomicAdd(&g_mD[(c0 + j) & 1023], acc[j] * acc[j]);
    }
    float* dp = out_z + (size_t)b * TD + c0;
    *(float4*)dp = *(float4*)&o[0];
    *(float4*)(dp + 4) = *(float4*)&o[4];
}

__global__ __launch_bounds__(256) void softmax_kernel()
{
    int p = blockIdx.x, tid = threadIdx.x;
    float x[8];
#pragma unroll
    for (int j = 0; j < 8; j++) x[j] = g_attraw[p * NB + tid + j * 256];
    __shared__ float red[256];
    float m = x[0];
#pragma unroll
    for (int j = 1; j < 8; j++) m = fmaxf(m, x[j]);
    red[tid] = m; __syncthreads();
    for (int off = 128; off > 0; off >>= 1) {
        if (tid < off) red[tid] = fmaxf(red[tid], red[tid + off]);
        __syncthreads();
    }
    m = red[0]; __syncthreads();
    float s = 0.f;
#pragma unroll
    for (int j = 0; j < 8; j++) { x[j] = expf(x[j] - m); s += x[j]; }
    red[tid] = s; __syncthreads();
    for (int off = 128; off > 0; off >>= 1) {
        if (tid < off) red[tid] += red[tid + off];
        __syncthreads();
    }
    float inv = 1.f / red[0];
#pragma unroll
    for (int j = 0; j < 8; j++) g_att[p * NB + tid + j * 256] = x[j] * inv;
}

__global__ __launch_bounds__(256) void zatt_kernel(
    const float* __restrict__ prev, const float* __restrict__ lambda2)
{
    int b = blockIdx.x, tid = threadIdx.x;
    __shared__ float a[NP];
    if (tid < NP) a[tid] = g_att[tid * NB + b];
    __syncthreads();
    float l2 = *lambda2;
#pragma unroll
    for (int j = 0; j < 8; j++) {
        int d = tid + j * 256;
        float s = 0.f;
#pragma unroll
        for (int p = 0; p < NP; p++) {
            float w = prev[((size_t)p * NB + b) * TD + d];
            w = fminf(fmaxf(w, -150.f), 150.f);
            s = fmaf(w, a[p], s);
        }
        g_V[(size_t)b * TD + d] = l2 * s;    // z_att
    }
}

// ------- spectrum normalize -----------------------------------------
__global__ void zero_mD_kernel() { g_mD[threadIdx.x] = 0.f; }

__global__ __launch_bounds__(256) void norm_kernel(float* __restrict__ out)
{
    int tid = threadIdx.x;
    float x[4];
#pragma unroll
    for (int j = 0; j < 4; j++) x[j] = g_mD[tid + j * 256];
    __shared__ float rmn[256], rmx[256];
    float mn = x[0], mx = x[0];
#pragma unroll
    for (int j = 1; j < 4; j++) { mn = fminf(mn, x[j]); mx = fmaxf(mx, x[j]); }
    rmn[tid] = mn; rmx[tid] = mx; __syncthreads();
    for (int off = 128; off > 0; off >>= 1) {
        if (tid < off) {
            rmn[tid] = fminf(rmn[tid], rmn[tid + off]);
            rmx[tid] = fmaxf(rmx[tid], rmx[tid + off]);
        }
        __syncthreads();
    }
    mn = rmn[0]; mx = rmx[0];
    float inv = 1.f / (mx - mn + 1e-8f);
#pragma unroll
    for (int j = 0; j < 4; j++) out[tid + j * 256] = (x[j] - mn) * inv;
}

// ------------------------------- driver ---------------------------------
extern "C" void kernel_launch(void* const* d_in, const int* in_sizes, int n_in,
                              void* d_out, int out_size)
{
    const float* x       = (const float*)d_in[0];  // (2048, 2048)
    const float* prev    = (const float*)d_in[1];  // (8, 2048, 2048)
    const float* Wd      = (const float*)d_in[2];  // (2048, 2048)
    const float* S       = (const float*)d_in[3];  // (2048, 2048), symmetric
    const float* lambda2 = (const float*)d_in[4];  // scalar

    float* out    = (float*)d_out;
    float* out_mD = out;           // (1024,)
    float* out_z  = out + 1024;    // (2048, 2048)

    float *pB, *pM, *pT, *pV;
    __nv_bfloat16 *wh, *wm, *wl, *wth, *wtm, *wtl;
    cudaGetSymbolAddress((void**)&pB, g_B);
    cudaGetSymbolAddress((void**)&pM, g_M);
    cudaGetSymbolAddress((void**)&pT, g_T);
    cudaGetSymbolAddress((void**)&pV, g_V);
    cudaGetSymbolAddress((void**)&wh, g_wh);   cudaGetSymbolAddress((void**)&wm, g_wm);
    cudaGetSymbolAddress((void**)&wl, g_wl);
    cudaGetSymbolAddress((void**)&wth, g_wth); cudaGetSymbolAddress((void**)&wtm, g_wtm);
    cudaGetSymbolAddress((void**)&wtl, g_wtl);

    const int SMEM3 = 3 * 2 * 16384 * 2;   // 196608
    cudaFuncSetAttribute(mma_gemm_kernel<3>,
                         cudaFuncAttributeMaxDynamicSharedMemorySize, SMEM3);

    const int SPLIT_BLKS = (int)(((size_t)TD * TD) / 1024);
    dim3 g16(16, 16);

    zero_mD_kernel<<<1, 1024>>>();
    // B = x @ Wd^T  (fp32 ascending-k chain via FFMA2: selection-critical)
    sgemm3_kernel<1, 0><<<g16, 128>>>(x, Wd, nullptr, pB);
    // z1, z2 fused (sorted sparse sums; +B last to match ref rounding)
    z1z2_kernel<<<NB, 256>>>(S);
    // M = Wd @ Wd  (tensor 3-split; feeds softmax only)
    split3_kernel<<<SPLIT_BLKS, 256>>>(Wd, wh, wm, wl);
    tsplit3_kernel<<<dim3(64, 64), dim3(32, 8)>>>(Wd, wth, wtm, wtl);
    mma_gemm_kernel<3><<<g16, 256, SMEM3>>>(wh, wm, wl, wth, wtm, wtl, pM);
    // v + attention dots fused (v never touches HBM)
    vatt_kernel<<<NB, 256>>>(pM, prev);
    softmax_kernel<<<NP, 256>>>();
    zatt_kernel<<<NB, 256>>>(prev, lambda2);
    // LIHT iter 1 (dense): T = z_att @ S + B  (fp32 chain, +B last)
    sgemm3_kernel<0, 1><<<g16, 128>>>(pV, S, pB, pT);
    thr_kernel<<<NB, 256>>>(pT);
    // LIHT iters 2..10 fused + spectrum + dense out
    liht_kernel<<<NB, 256>>>(S, out_z);
    norm_kernel<<<1, 256>>>(out_mD);

    (void)in_sizes; (void)n_in; (void)out_size;
}